// round 7
// baseline (speedup 1.0000x reference)
#include <cuda_runtime.h>
#include <cuda_bf16.h>
#include <math.h>
#include <stdint.h>

#define NN   512
#define NP   (NN*NN)        // 262144
#define FIN  16
#define TWOF 32
#define EE   16384
#define NL   3

// g_ST layout
#define ST_SUM   0
#define ST_SQ    64
#define ST_TR    128
#define ST_S     192
#define ST_T     256
#define ST_ATR   320

typedef __nv_bfloat16 bf16;
typedef __nv_bfloat162 bf162;

// ---------------- scratch (device globals; no allocation allowed) ----------
__device__ float g_U [32u*NP];        // fp32 adjacency (scatter target)
__device__ bf16  g_Ub[32u*NP];        // bf16 adjacency
__device__ bf16  g_V0[64u*NP];
__device__ bf16  g_V1[64u*NP];
__device__ bf16  g_O1[64u*NP];
__device__ bf16  g_O2[64u*NP];
__device__ bf16  g_M [64u*NP];
__device__ float g_ST[448];
__device__ float g_AC[64];

#define MMA_BF16(d, a, b)                                                      \
    asm volatile(                                                              \
        "mma.sync.aligned.m16n8k16.row.col.f32.bf16.bf16.f32 "                 \
        "{%0,%1,%2,%3},{%4,%5,%6,%7},{%8,%9},{%0,%1,%2,%3};"                   \
        : "+f"(d[0]), "+f"(d[1]), "+f"(d[2]), "+f"(d[3])                       \
        : "r"(a[0]), "r"(a[1]), "r"(a[2]), "r"(a[3]), "r"(b[0]), "r"(b[1]))

#define LDSM4(R, addr)                                                         \
    asm volatile("ldmatrix.sync.aligned.m8n8.x4.shared.b16 {%0,%1,%2,%3},[%4];"\
        : "=r"(R[0]), "=r"(R[1]), "=r"(R[2]), "=r"(R[3]) : "r"(addr))

#define LDSM4T(R, addr)                                                        \
    asm volatile("ldmatrix.sync.aligned.m8n8.x4.trans.shared.b16 {%0,%1,%2,%3},[%4];"\
        : "=r"(R[0]), "=r"(R[1]), "=r"(R[2]), "=r"(R[3]) : "r"(addr))

__device__ __forceinline__ uint32_t smaddr(const void* p) {
    return (uint32_t)__cvta_generic_to_shared(p);
}
__device__ __forceinline__ void cp16(void* smem, const void* g) {
    asm volatile("cp.async.cg.shared.global [%0], [%1], 16;"
                 :: "r"(smaddr(smem)), "l"(g));
}

// ---------------- init ------------------------------------------------------
__global__ void k_zero(float* U, float* AC, float* ST) {
    int i = blockIdx.x * 256 + threadIdx.x;           // 32*NP threads
    U[i] = 0.f;
    if (i < 64)  AC[i] = 0.f;
    if (i < 448) ST[i] = 0.f;
}

// ---------------- scatter edges into A[c][src][dst] -------------------------
__global__ void k_scatter(const float* __restrict__ x, const int* __restrict__ ei,
                          float* __restrict__ A) {
    int t = blockIdx.x * 256 + threadIdx.x;           // EE*32 threads
    int e = t >> 5, c = t & 31;
    int s = ei[e], d = ei[EE + e];
    float v = (c < FIN) ? x[s * FIN + c] : x[d * FIN + (c - FIN)];
    atomicAdd(&A[(size_t)c * NP + s * NN + d], v);
}

// ---------------- per-channel trace + total (A), and fp32->bf16 convert ------
__global__ void k_ext_stats(const float* __restrict__ U, float* __restrict__ st,
                            bf16* __restrict__ Ub) {
    int c = blockIdx.x;
    const float* u = U + (size_t)c * NP;
    bf16* ub = Ub + (size_t)c * NP;
    float tot = 0.f, tr = 0.f;
    for (int i = threadIdx.x; i < NP;  i += 256) {
        float v = u[i];
        tot += v;
        ub[i] = __float2bfloat16_rn(v);
    }
    for (int i = threadIdx.x; i < NN;  i += 256) tr  += u[i * (NN + 1)];
    __shared__ float s1[256], s2[256];
    s1[threadIdx.x] = tot; s2[threadIdx.x] = tr; __syncthreads();
    for (int o = 128; o > 0; o >>= 1) {
        if (threadIdx.x < o) { s1[threadIdx.x] += s1[threadIdx.x+o]; s2[threadIdx.x] += s2[threadIdx.x+o]; }
        __syncthreads();
    }
    if (threadIdx.x == 0) { st[c] = s2[0]; st[64 + c] = s1[0]; }
}

// ---------------- extractor combine for A (C=32), smem-staged weights --------
__global__ void k_ext_combine(const float* __restrict__ st,
                              const float* __restrict__ w1, const float* __restrict__ b1,
                              const float* __restrict__ w2, const float* __restrict__ w3,
                              float* __restrict__ acc) {
    __shared__ float w1s[64 * 32], w2s[64 * 32], w3s[64 * 64], osh[64];
    int tid = threadIdx.x;                              // 256 threads
    for (int i = tid * 4; i < 64 * 32; i += 1024) {
        *(float4*)(w1s + i) = *(const float4*)(w1 + i);
        *(float4*)(w2s + i) = *(const float4*)(w2 + i);
    }
    for (int i = tid * 4; i < 64 * 64; i += 1024)
        *(float4*)(w3s + i) = *(const float4*)(w3 + i);
    __syncthreads();
    if (tid < 64) {
        int h = tid;
        float o = b1[h];
        for (int c = 0; c < 32; c++) {
            float tr = st[c];
            float s  = (st[64 + c] - tr) / (512.f * 511.f);
            o += w1s[h * 32 + c] * (tr / 512.f) + w2s[h * 32 + c] * s;
        }
        osh[h] = o;
    }
    __syncthreads();
    if (tid < 64) {
        int h = tid;
        float a = osh[h];
        for (int k = 0; k < 64; k++) a += w3s[h * 64 + k] * fmaxf(osh[k], 0.f);
        acc[h] += a;
    }
}

// ---------------- fused mix1+mix2, bf16 mma (BN folded) ----------------------
__global__ __launch_bounds__(256) void k_mixAB(
    const bf16* __restrict__ in, int Ct,
    const float* __restrict__ W1, const float* __restrict__ b1,
    const float* __restrict__ W2, const float* __restrict__ b2,
    const float* __restrict__ ST, int fold,
    bf16* __restrict__ O1, bf16* __restrict__ O2) {
    const int ld2 = Ct + 8;                 // row stride: (Ct+8)*2B = 16*odd
    extern __shared__ char shraw[];
    bf16*  Ws1 = (bf16*)shraw;              // [64][ld2]
    bf16*  Ws2 = Ws1 + 64 * ld2;
    float* bs1 = (float*)(Ws2 + 64 * ld2);
    float* bs2 = bs1 + 64;
    bf16*  Us  = (bf16*)(bs2 + 64);         // [32][136]

    for (int i = threadIdx.x; i < 64 * Ct; i += 256) {
        int o = i / Ct, c = i - o * Ct;
        float s = fold ? ST[ST_S + c] : 1.f;
        Ws1[o * ld2 + c] = __float2bfloat16_rn(W1[i] * s);
        Ws2[o * ld2 + c] = __float2bfloat16_rn(W2[i] * s);
    }
    if (threadIdx.x < 64) {
        int o = threadIdx.x;
        float a1 = b1[o], a2 = b2[o];
        if (fold)
            for (int c = 0; c < Ct; c++) {
                float t = ST[ST_T + c];
                a1 += W1[o * Ct + c] * t;
                a2 += W2[o * Ct + c] * t;
            }
        bs1[o] = a1; bs2[o] = a2;
    }

    const int p0   = blockIdx.x * 128;
    const int lane = threadIdx.x & 31;
    const int wid  = threadIdx.x >> 5;
    const int cg = wid & 3, rg = wid >> 2;
    const int lq = lane & 3, lr = lane >> 2;
    const int lml = lane & 15, lmh = (lane >> 4) << 3;

    float acc1[2][4][4], acc2[2][4][4];
#pragma unroll
    for (int mi = 0; mi < 2; mi++)
#pragma unroll
        for (int nj = 0; nj < 4; nj++)
#pragma unroll
            for (int q = 0; q < 4; q++) { acc1[mi][nj][q] = 0.f; acc2[mi][nj][q] = 0.f; }

    for (int k0 = 0; k0 < Ct; k0 += 32) {
        __syncthreads();
        for (int i = threadIdx.x; i < 512; i += 256) {        // 32 rows x 128 bf16
            int kk = i >> 4, c8 = (i & 15) << 3;
            *(float4*)(Us + kk * 136 + c8) =
                *(const float4*)(in + (size_t)(k0 + kk) * NP + p0 + c8);
        }
        __syncthreads();
#pragma unroll
        for (int kk = 0; kk < 32; kk += 16) {
            uint32_t a1[2][4], a2[2][4], bq[2][4];
#pragma unroll
            for (int mi = 0; mi < 2; mi++) {
                int r = rg * 32 + mi * 16 + lml;
                LDSM4(a1[mi], smaddr(Ws1 + r * ld2 + k0 + kk + lmh));
                LDSM4(a2[mi], smaddr(Ws2 + r * ld2 + k0 + kk + lmh));
            }
#pragma unroll
            for (int njp = 0; njp < 2; njp++)
                LDSM4T(bq[njp], smaddr(Us + (kk + lml) * 136 + cg * 32 + njp * 16 + lmh));
#pragma unroll
            for (int mi = 0; mi < 2; mi++)
#pragma unroll
                for (int njp = 0; njp < 2; njp++) {
                    MMA_BF16(acc1[mi][2*njp],   a1[mi], (bq[njp]));
                    MMA_BF16(acc1[mi][2*njp+1], a1[mi], (bq[njp]+2));
                    MMA_BF16(acc2[mi][2*njp],   a2[mi], (bq[njp]));
                    MMA_BF16(acc2[mi][2*njp+1], a2[mi], (bq[njp]+2));
                }
        }
    }

#pragma unroll
    for (int mi = 0; mi < 2; mi++) {
        int o0 = rg * 32 + mi * 16 + lr, o1 = o0 + 8;
        float c10 = bs1[o0], c11 = bs1[o1], c20 = bs2[o0], c21 = bs2[o1];
#pragma unroll
        for (int nj = 0; nj < 4; nj++) {
            int col = p0 + cg * 32 + nj * 8 + 2 * lq;
            *(bf162*)(O1 + (size_t)o0 * NP + col) =
                __floats2bfloat162_rn(acc1[mi][nj][0] + c10, acc1[mi][nj][1] + c10);
            *(bf162*)(O1 + (size_t)o1 * NP + col) =
                __floats2bfloat162_rn(acc1[mi][nj][2] + c11, acc1[mi][nj][3] + c11);
            *(bf162*)(O2 + (size_t)o0 * NP + col) =
                __floats2bfloat162_rn(acc2[mi][nj][0] + c20, acc2[mi][nj][1] + c20);
            *(bf162*)(O2 + (size_t)o1 * NP + col) =
                __floats2bfloat162_rn(acc2[mi][nj][2] + c21, acc2[mi][nj][3] + c21);
        }
    }
}

// ---------------- batched 512^3 bf16 GEMM, 3-stage cp.async, BK=32 -----------
#define LDA 40      // 80B row stride (conflict-free LDSM)
#define LDB 136     // 272B row stride
#define STG (128*LDA + 32*LDB)   // 9472 bf16 per stage
__global__ __launch_bounds__(256) void k_mma(const bf16* __restrict__ A,
                                             const bf16* __restrict__ B,
                                             bf16* __restrict__ C) {
    extern __shared__ bf16 dsm[];                  // 3 stages
    const int ch = blockIdx.z;
    const bf16* Ab = A + (size_t)ch * NP;
    const bf16* Bb = B + (size_t)ch * NP;
    bf16*       Cb = C + (size_t)ch * NP;
    const int tid  = threadIdx.x;
    const int lane = tid & 31, wid = tid >> 5;
    const int wr = wid >> 1, wc = wid & 1;
    const int lq = lane & 3, lr = lane >> 2;
    const int lml = lane & 15, lmh = (lane >> 4) << 3;
    const int rowBase = blockIdx.y * 128;
    const int colBase = blockIdx.x * 128;

    float acc[2][8][4];
#pragma unroll
    for (int mi = 0; mi < 2; mi++)
#pragma unroll
        for (int nj = 0; nj < 8; nj++)
#pragma unroll
            for (int q = 0; q < 4; q++) acc[mi][nj][q] = 0.f;

    auto loadTile = [&](int t, int s) {
        bf16* As = dsm + s * STG;
        bf16* Bs = As + 128 * LDA;
        int k0 = t * 32;
#pragma unroll
        for (int i = 0; i < 2; i++) {              // A: 128 rows x 32 bf16
            int lin = tid + i * 256;
            int r = lin >> 2, kc = (lin & 3) << 3;
            cp16(As + r * LDA + kc, Ab + (size_t)(rowBase + r) * NN + k0 + kc);
        }
#pragma unroll
        for (int i = 0; i < 2; i++) {              // B: 32 rows x 128 bf16
            int lin = tid + i * 256;
            int kk = lin >> 4, c8 = (lin & 15) << 3;
            cp16(Bs + kk * LDB + c8, Bb + (size_t)(k0 + kk) * NN + colBase + c8);
        }
        asm volatile("cp.async.commit_group;");
    };

    loadTile(0, 0);
    loadTile(1, 1);
    for (int t = 0; t < 16; t++) {                 // 16 k-tiles of 32
        asm volatile("cp.async.wait_group 1;");
        __syncthreads();
        if (t + 2 < 16) loadTile(t + 2, (t + 2) % 3);
        const bf16* As = dsm + (t % 3) * STG;
        const bf16* Bs = As + 128 * LDA;
#pragma unroll
        for (int kk = 0; kk < 32; kk += 16) {
            uint32_t a[2][4], bq[4][4];
#pragma unroll
            for (int mi = 0; mi < 2; mi++) {
                int r = wr * 32 + mi * 16 + lml;
                LDSM4(a[mi], smaddr(As + r * LDA + kk + lmh));
            }
#pragma unroll
            for (int njp = 0; njp < 4; njp++)
                LDSM4T(bq[njp], smaddr(Bs + (kk + lml) * LDB + wc * 64 + njp * 16 + lmh));
#pragma unroll
            for (int mi = 0; mi < 2; mi++)
#pragma unroll
                for (int njp = 0; njp < 4; njp++) {
                    MMA_BF16(acc[mi][2*njp],   a[mi], (bq[njp]));
                    MMA_BF16(acc[mi][2*njp+1], a[mi], (bq[njp]+2));
                }
        }
        __syncthreads();
    }

#pragma unroll
    for (int mi = 0; mi < 2; mi++) {
        int r0 = rowBase + wr * 32 + mi * 16 + lr;
#pragma unroll
        for (int nj = 0; nj < 8; nj++) {
            int col = colBase + wc * 64 + nj * 8 + 2 * lq;
            *(bf162*)(Cb + (size_t)r0 * NN + col) =
                __floats2bfloat162_rn(acc[mi][nj][0], acc[mi][nj][1]);
            *(bf162*)(Cb + (size_t)(r0 + 8) * NN + col) =
                __floats2bfloat162_rn(acc[mi][nj][2], acc[mi][nj][3]);
        }
    }
}

// ---------------- mix4: concat(M, cur) -> out (bf16), stats epilogue ---------
__global__ __launch_bounds__(256) void k_mix4(
    const bf16* __restrict__ Mt, const bf16* __restrict__ cur, int C2,
    const float* __restrict__ W, const float* __restrict__ bias,
    int fold, bf16* __restrict__ out, float* __restrict__ ST) {
    const int Ct = 64 + C2;
    const int ld2 = Ct + 8;
    extern __shared__ char shraw[];
    bf16*  Ws = (bf16*)shraw;               // [64][ld2]
    float* bs = (float*)(Ws + 64 * ld2);    // 64
    bf16*  Us = (bf16*)(bs + 64);           // [32][136]
    float* sSum = (float*)(Us + 32 * 136);  // 64
    float* sSq  = sSum + 64;                // 64
    float* sTr  = sSq + 64;                 // 64

    for (int i = threadIdx.x; i < 64 * Ct; i += 256) {
        int o = i / Ct, c = i - o * Ct;
        float s = (c >= 64 && fold) ? ST[ST_S + c - 64] : 1.f;
        Ws[o * ld2 + c] = __float2bfloat16_rn(W[i] * s);
    }
    if (threadIdx.x < 64) {
        int o = threadIdx.x;
        float a = bias[o];
        if (fold)
            for (int c = 64; c < Ct; c++) a += W[o * Ct + c] * ST[ST_T + c - 64];
        bs[o] = a;
    }
    if (threadIdx.x < 192) sSum[threadIdx.x] = 0.f;   // zeros sum/sq/tr

    const int p0   = blockIdx.x * 128;
    const int lane = threadIdx.x & 31;
    const int wid  = threadIdx.x >> 5;
    const int cg = wid & 3, rg = wid >> 2;
    const int lq = lane & 3, lr = lane >> 2;
    const int lml = lane & 15, lmh = (lane >> 4) << 3;

    float acc[2][4][4];
#pragma unroll
    for (int mi = 0; mi < 2; mi++)
#pragma unroll
        for (int nj = 0; nj < 4; nj++)
#pragma unroll
            for (int q = 0; q < 4; q++) acc[mi][nj][q] = 0.f;

    for (int k0 = 0; k0 < Ct; k0 += 32) {
        __syncthreads();
        for (int i = threadIdx.x; i < 512; i += 256) {
            int kk = i >> 4, c8 = (i & 15) << 3;
            int c = k0 + kk;
            const bf16* src = (c < 64) ? Mt + (size_t)c * NP
                                       : cur + (size_t)(c - 64) * NP;
            *(float4*)(Us + kk * 136 + c8) = *(const float4*)(src + p0 + c8);
        }
        __syncthreads();
#pragma unroll
        for (int kk = 0; kk < 32; kk += 16) {
            uint32_t a[2][4], bq[2][4];
#pragma unroll
            for (int mi = 0; mi < 2; mi++) {
                int r = rg * 32 + mi * 16 + lml;
                LDSM4(a[mi], smaddr(Ws + r * ld2 + k0 + kk + lmh));
            }
#pragma unroll
            for (int njp = 0; njp < 2; njp++)
                LDSM4T(bq[njp], smaddr(Us + (kk + lml) * 136 + cg * 32 + njp * 16 + lmh));
#pragma unroll
            for (int mi = 0; mi < 2; mi++)
#pragma unroll
                for (int njp = 0; njp < 2; njp++) {
                    MMA_BF16(acc[mi][2*njp],   a[mi], (bq[njp]));
                    MMA_BF16(acc[mi][2*njp+1], a[mi], (bq[njp]+2));
                }
        }
    }
    __syncthreads();

    int dp = ((p0 + 512) / 513) * 513;          // diagonal column inside block
    bool hasDiag = (dp < p0 + 128);

#pragma unroll
    for (int mi = 0; mi < 2; mi++) {
        int o0 = rg * 32 + mi * 16 + lr, o1 = o0 + 8;
        float b0 = bs[o0], b1v = bs[o1];
        float s0 = 0.f, q0 = 0.f, s1 = 0.f, q1 = 0.f;
#pragma unroll
        for (int nj = 0; nj < 4; nj++) {
            int col = p0 + cg * 32 + nj * 8 + 2 * lq;
            float v00 = acc[mi][nj][0] + b0, v01 = acc[mi][nj][1] + b0;
            float v10 = acc[mi][nj][2] + b1v, v11 = acc[mi][nj][3] + b1v;
            if (out) {
                *(bf162*)(out + (size_t)o0 * NP + col) = __floats2bfloat162_rn(v00, v01);
                *(bf162*)(out + (size_t)o1 * NP + col) = __floats2bfloat162_rn(v10, v11);
            }
            s0 += v00 + v01; q0 += v00 * v00 + v01 * v01;
            s1 += v10 + v11; q1 += v10 * v10 + v11 * v11;
            if (hasDiag) {
                if (col == dp)     { atomicAdd(&sTr[o0], v00); atomicAdd(&sTr[o1], v10); }
                if (col + 1 == dp) { atomicAdd(&sTr[o0], v01); atomicAdd(&sTr[o1], v11); }
            }
        }
#pragma unroll
        for (int off = 1; off < 4; off <<= 1) {
            s0 += __shfl_xor_sync(0xffffffffu, s0, off);
            q0 += __shfl_xor_sync(0xffffffffu, q0, off);
            s1 += __shfl_xor_sync(0xffffffffu, s1, off);
            q1 += __shfl_xor_sync(0xffffffffu, q1, off);
        }
        if (lq == 0) {
            atomicAdd(&sSum[o0], s0); atomicAdd(&sSq[o0], q0);
            atomicAdd(&sSum[o1], s1); atomicAdd(&sSq[o1], q1);
        }
    }
    __syncthreads();
    if (threadIdx.x < 64) {
        int c = threadIdx.x;
        atomicAdd(&ST[ST_SUM + c], sSum[c]);
        atomicAdd(&ST[ST_SQ  + c], sSq[c]);
        if (sTr[c] != 0.f) atomicAdd(&ST[ST_TR + c], sTr[c]);
    }
}

// ---------------- finalize: BN params + analytic extractor (smem-staged) -----
__global__ void k_finalize(float* __restrict__ ST,
                           const float* __restrict__ g, const float* __restrict__ b,
                           const float* __restrict__ w1, const float* __restrict__ b1,
                           const float* __restrict__ w2, const float* __restrict__ w3,
                           float* __restrict__ acc) {
    __shared__ float w1s[64 * 64], w2s[64 * 64], w3s[64 * 64];
    __shared__ float str[64], stot[64], osh[64];
    int tid = threadIdx.x;                              // 256 threads
    for (int i = tid * 4; i < 64 * 64; i += 1024) {
        *(float4*)(w1s + i) = *(const float4*)(w1 + i);
        *(float4*)(w2s + i) = *(const float4*)(w2 + i);
        *(float4*)(w3s + i) = *(const float4*)(w3 + i);
    }
    if (tid < 64) {
        int h = tid;
        float sum = ST[ST_SUM + h], sq = ST[ST_SQ + h], tr = ST[ST_TR + h];
        float m   = sum / (float)NP;
        float var = sq / (float)NP - m * m;
        float s   = g[h] * rsqrtf(var + 1e-5f);
        float t   = b[h] - m * s;
        ST[ST_S + h] = s; ST[ST_T + h] = t;
        ST[ST_SUM + h] = 0.f; ST[ST_SQ + h] = 0.f; ST[ST_TR + h] = 0.f;
        str[h]  = tr * s + 512.f * t;
        stot[h] = sum * s + (float)NP * t;
    }
    __syncthreads();
    if (tid < 64) {
        int h = tid;
        float o = b1[h];
        for (int c = 0; c < 64; c++) {
            float trc = str[c];
            float sc  = (stot[c] - trc) / (512.f * 511.f);
            o += w1s[h * 64 + c] * (trc / 512.f) + w2s[h * 64 + c] * sc;
        }
        osh[h] = o;
    }
    __syncthreads();
    if (tid < 64) {
        int h = tid;
        float a = osh[h];
        for (int k = 0; k < 64; k++) a += w3s[h * 64 + k] * fmaxf(osh[k], 0.f);
        acc[h] += a;
    }
}

// ---------------- head (smem-staged weights) ---------------------------------
__global__ void k_head(const float* __restrict__ acc,
                       const float* __restrict__ ac_w, const float* __restrict__ ac_b,
                       const float* __restrict__ fl_w, const float* __restrict__ fl_b,
                       float* __restrict__ out) {
    __shared__ float aw[64 * 64], fw[10 * 64];
    __shared__ float o[64], t[64], lg[10];
    int tid = threadIdx.x;                              // 256 threads
    for (int i = tid * 4; i < 64 * 64; i += 1024)
        *(float4*)(aw + i) = *(const float4*)(ac_w + i);
    for (int i = tid * 4; i < 10 * 64; i += 1024)
        *(float4*)(fw + i) = *(const float4*)(fl_w + i);
    if (tid < 64) o[tid] = fmaxf(acc[tid], 0.f) / (float)NL;
    __syncthreads();
    if (tid < 64) {
        int h = tid;
        float s = ac_b[h];
        for (int k = 0; k < 64; k++) s += aw[h * 64 + k] * o[k];
        t[h] = o[h] + fmaxf(s, 0.f);
    }
    __syncthreads();
    if (tid < 10) {
        int h = tid;
        float l = fl_b[h];
        for (int k = 0; k < 64; k++) l += fw[h * 64 + k] * t[k];
        lg[h] = l;
    }
    __syncthreads();
    if (tid < 10) {
        float m = -1e30f;
        for (int i = 0; i < 10; i++) m = fmaxf(m, lg[i]);
        float se = 0.f;
        for (int i = 0; i < 10; i++) se += expf(lg[i] - m);
        out[tid] = lg[tid] - m - logf(se);
    }
}

// ---------------- launch -----------------------------------------------------
extern "C" void kernel_launch(void* const* d_in, const int* in_sizes, int n_in,
                              void* d_out, int out_size) {
    const float* x     = (const float*)d_in[0];
    const int*   ei    = (const int*)  d_in[1];
    const float* np1_w = (const float*)d_in[2];
    const float* np1_b = (const float*)d_in[3];
    const float* np2_w = (const float*)d_in[4];
    const float* np3_w = (const float*)d_in[5];
    const float* c0m1w = (const float*)d_in[6];
    const float* c0m1b = (const float*)d_in[7];
    const float* c0m2w = (const float*)d_in[8];
    const float* c0m2b = (const float*)d_in[9];
    const float* c0m4w = (const float*)d_in[10];
    const float* c0m4b = (const float*)d_in[11];
    const float* cm1w  = (const float*)d_in[12];
    const float* cm1b  = (const float*)d_in[13];
    const float* cm2w  = (const float*)d_in[14];
    const float* cm2b  = (const float*)d_in[15];
    const float* cm4w  = (const float*)d_in[16];
    const float* cm4b  = (const float*)d_in[17];
    const float* bn_g  = (const float*)d_in[18];
    const float* bn_b  = (const float*)d_in[19];
    const float* fe1w  = (const float*)d_in[20];
    const float* fe1b  = (const float*)d_in[21];
    const float* fe2w  = (const float*)d_in[22];
    const float* fe3w  = (const float*)d_in[23];
    const float* ac_w  = (const float*)d_in[24];
    const float* ac_b  = (const float*)d_in[25];
    const float* fl_w  = (const float*)d_in[26];
    const float* fl_b  = (const float*)d_in[27];

    float *U, *ST, *AC;
    bf16 *Ub, *V0, *V1, *O1, *O2, *M;
    cudaGetSymbolAddress((void**)&U,  g_U);
    cudaGetSymbolAddress((void**)&Ub, g_Ub);
    cudaGetSymbolAddress((void**)&V0, g_V0);
    cudaGetSymbolAddress((void**)&V1, g_V1);
    cudaGetSymbolAddress((void**)&O1, g_O1);
    cudaGetSymbolAddress((void**)&O2, g_O2);
    cudaGetSymbolAddress((void**)&M,  g_M);
    cudaGetSymbolAddress((void**)&ST, g_ST);
    cudaGetSymbolAddress((void**)&AC, g_AC);

    static bool attr_done = false;
    if (!attr_done) {
        cudaFuncSetAttribute(k_mma,   cudaFuncAttributeMaxDynamicSharedMemorySize, 3 * STG * 2);
        cudaFuncSetAttribute(k_mixAB, cudaFuncAttributeMaxDynamicSharedMemorySize, 64 * 1024);
        cudaFuncSetAttribute(k_mix4,  cudaFuncAttributeMaxDynamicSharedMemorySize, 64 * 1024);
        attr_done = true;
    }

    k_zero<<<(32u * NP) / 256, 256>>>(U, AC, ST);
    k_scatter<<<(EE * 32) / 256, 256>>>(x, ei, U);

    k_ext_stats<<<TWOF, 256>>>(U, ST + ST_ATR, Ub);
    k_ext_combine<<<1, 256>>>(ST + ST_ATR, np1_w, np1_b, np2_w, np3_w, AC);

    const bf16* cur = Ub;
    for (int l = 0; l < NL; l++) {
        const int Cin = l ? 64 : TWOF;
        const int fold = (l > 0) ? 1 : 0;
        const float* m1w = l ? cm1w + (l - 1) * 64 * 64  : c0m1w;
        const float* m1b = l ? cm1b + (l - 1) * 64       : c0m1b;
        const float* m2w = l ? cm2w + (l - 1) * 64 * 64  : c0m2w;
        const float* m2b = l ? cm2b + (l - 1) * 64       : c0m2b;
        const float* m4w = l ? cm4w + (l - 1) * 64 * 128 : c0m4w;
        const float* m4b = l ? cm4b + (l - 1) * 64       : c0m4b;

        int ldab = Cin + 8;
        size_t shAB = (size_t)(2 * 64 * ldab + 32 * 136) * 2 + 2 * 64 * 4;
        k_mixAB<<<2048, 256, shAB>>>(cur, Cin, m1w, m1b, m2w, m2b, ST, fold, O1, O2);

        k_mma<<<dim3(4, 4, 64), 256, 3 * STG * 2>>>(O1, O2, M);

        bf16* nxt = (l == 0) ? V0 : ((l == 1) ? V1 : nullptr);
        int ld4 = 64 + Cin + 8;
        size_t sh4 = (size_t)(64 * ld4 + 32 * 136) * 2 + (64 + 192) * 4;
        k_mix4<<<2048, 256, sh4>>>(M, cur, Cin, m4w, m4b, fold, nxt, ST);

        k_finalize<<<1, 256>>>(ST, bn_g + 64 * l, bn_b + 64 * l,
                               fe1w + l * 64 * 64, fe1b + l * 64,
                               fe2w + l * 64 * 64, fe3w + l * 64 * 64, AC);

        cur = nxt;
    }

    k_head<<<1, 256>>>(AC, ac_w, ac_b, fl_w, fl_b, (float*)d_out);
}

// round 11
// speedup vs baseline: 1.1590x; 1.1590x over previous
#include <cuda_runtime.h>
#include <cuda_bf16.h>
#include <math.h>
#include <stdint.h>

#define NN   512
#define NP   (NN*NN)        // 262144
#define FIN  16
#define TWOF 32
#define EE   16384
#define NL   3

// g_ST layout
#define ST_SUM   0
#define ST_SQ    64
#define ST_TR    128
#define ST_S     192
#define ST_T     256
#define ST_ATR   320

typedef __nv_bfloat16 bf16;
typedef __nv_bfloat162 bf162;

// ---------------- scratch (device globals; no allocation allowed) ----------
__device__ bf16  g_Ub[32u*NP];        // bf16 adjacency (scatter target)
__device__ bf16  g_V0[64u*NP];
__device__ bf16  g_V1[64u*NP];
__device__ bf16  g_O1[64u*NP];
__device__ bf16  g_O2[64u*NP];
__device__ bf16  g_M [64u*NP];
__device__ float g_ST[448];
__device__ float g_AC[64];

#define MMA_BF16(d, a, b)                                                      \
    asm volatile(                                                              \
        "mma.sync.aligned.m16n8k16.row.col.f32.bf16.bf16.f32 "                 \
        "{%0,%1,%2,%3},{%4,%5,%6,%7},{%8,%9},{%0,%1,%2,%3};"                   \
        : "+f"(d[0]), "+f"(d[1]), "+f"(d[2]), "+f"(d[3])                       \
        : "r"(a[0]), "r"(a[1]), "r"(a[2]), "r"(a[3]), "r"(b[0]), "r"(b[1]))

#define LDSM4(R, addr)                                                         \
    asm volatile("ldmatrix.sync.aligned.m8n8.x4.shared.b16 {%0,%1,%2,%3},[%4];"\
        : "=r"(R[0]), "=r"(R[1]), "=r"(R[2]), "=r"(R[3]) : "r"(addr))

#define LDSM4T(R, addr)                                                        \
    asm volatile("ldmatrix.sync.aligned.m8n8.x4.trans.shared.b16 {%0,%1,%2,%3},[%4];"\
        : "=r"(R[0]), "=r"(R[1]), "=r"(R[2]), "=r"(R[3]) : "r"(addr))

__device__ __forceinline__ uint32_t smaddr(const void* p) {
    return (uint32_t)__cvta_generic_to_shared(p);
}
__device__ __forceinline__ void cp16(void* smem, const void* g) {
    asm volatile("cp.async.cg.shared.global [%0], [%1], 16;"
                 :: "r"(smaddr(smem)), "l"(g));
}

// ---------------- init: zero bf16 adjacency + AC + ST ------------------------
__global__ void k_zero(uint32_t* Ub32, float* AC, float* ST) {
    int i = blockIdx.x * 256 + threadIdx.x;           // 16*NP u32 words
    Ub32[i] = 0u;
    if (i < 64)  AC[i] = 0.f;
    if (i < 448) ST[i] = 0.f;
}

// ---------------- scatter edges into A[c][src][dst] (bf16 atomics) -----------
__global__ void k_scatter(const float* __restrict__ x, const int* __restrict__ ei,
                          bf16* __restrict__ A) {
    int t = blockIdx.x * 256 + threadIdx.x;           // EE*32 threads
    int e = t >> 5, c = t & 31;
    int s = ei[e], d = ei[EE + e];
    float v = (c < FIN) ? x[s * FIN + c] : x[d * FIN + (c - FIN)];
    atomicAdd(&A[(size_t)c * NP + s * NN + d], __float2bfloat16_rn(v));
}

// ---------------- per-channel trace + total of A (bf16 in, fp32 reduce) ------
__global__ void k_ext_stats(const bf16* __restrict__ U, float* __restrict__ st) {
    int c = blockIdx.x;
    const bf16* u = U + (size_t)c * NP;
    const uint4* u8 = (const uint4*)u;                // 8 bf16 per uint4
    float tot = 0.f, tr = 0.f;
    for (int i = threadIdx.x; i < NP / 8; i += 256) {
        uint4 v = u8[i];
        float2 f0 = __bfloat1622float2(*(bf162*)&v.x);
        float2 f1 = __bfloat1622float2(*(bf162*)&v.y);
        float2 f2 = __bfloat1622float2(*(bf162*)&v.z);
        float2 f3 = __bfloat1622float2(*(bf162*)&v.w);
        tot += (f0.x + f0.y) + (f1.x + f1.y) + (f2.x + f2.y) + (f3.x + f3.y);
    }
    for (int i = threadIdx.x; i < NN; i += 256) tr += __bfloat162float(u[i * (NN + 1)]);
    __shared__ float s1[256], s2[256];
    s1[threadIdx.x] = tot; s2[threadIdx.x] = tr; __syncthreads();
    for (int o = 128; o > 0; o >>= 1) {
        if (threadIdx.x < o) { s1[threadIdx.x] += s1[threadIdx.x+o]; s2[threadIdx.x] += s2[threadIdx.x+o]; }
        __syncthreads();
    }
    if (threadIdx.x == 0) { st[c] = s2[0]; st[64 + c] = s1[0]; }
}

// ---------------- fused mix1+mix2 (+ BN fold + prev-layer extractor flush) ---
__global__ __launch_bounds__(256) void k_mixAB(
    const bf16* __restrict__ in, int Ct,
    const float* __restrict__ W1, const float* __restrict__ b1,
    const float* __restrict__ W2, const float* __restrict__ b2,
    const float* __restrict__ ST, int fold,
    const float* __restrict__ bng, const float* __restrict__ bnb,
    const float* __restrict__ STA,       // adjacency stats (layer 0) or null
    const float* __restrict__ ew1, const float* __restrict__ eb1,
    const float* __restrict__ ew2, const float* __restrict__ ew3, int eC,
    float* __restrict__ AC,
    bf16* __restrict__ O1, bf16* __restrict__ O2) {
    const int ld2 = Ct + 8;                 // row stride: (Ct+8)*2B = 16*odd
    extern __shared__ char shraw[];
    bf16*  Ws1 = (bf16*)shraw;              // [64][ld2]
    bf16*  Ws2 = Ws1 + 64 * ld2;
    float* bs1 = (float*)(Ws2 + 64 * ld2);
    float* bs2 = bs1 + 64;
    bf16*  Us  = (bf16*)(bs2 + 64);         // [32][136]
    __shared__ float sS[64], sT[64], osh[64];

    // per-block BN params from raw stats (finalize folded in)
    if (fold && threadIdx.x < 64) {
        int c = threadIdx.x;
        float sum = ST[ST_SUM + c], sq = ST[ST_SQ + c];
        float m   = sum / (float)NP;
        float var = sq / (float)NP - m * m;
        float s   = bng[c] * rsqrtf(var + 1e-5f);
        sS[c] = s; sT[c] = bnb[c] - m * s;
    }
    __syncthreads();

    // block 0: flush previous stage's extractor into AC
    if (blockIdx.x == 0 && threadIdx.x < 64) {
        int h = threadIdx.x;
        float o = eb1[h];
        for (int c = 0; c < eC; c++) {
            float str, stot;
            if (STA) { str = STA[c]; stot = STA[64 + c]; }
            else {
                float s = sS[c], t = sT[c];
                str  = ST[ST_TR  + c] * s + 512.f * t;
                stot = ST[ST_SUM + c] * s + (float)NP * t;
            }
            o += ew1[h * eC + c] * (str / 512.f)
               + ew2[h * eC + c] * ((stot - str) / (512.f * 511.f));
        }
        osh[h] = o;
    }
    __syncthreads();
    if (blockIdx.x == 0 && threadIdx.x < 64) {
        int h = threadIdx.x;
        float a = osh[h];
        for (int k = 0; k < 64; k++) a += ew3[h * 64 + k] * fmaxf(osh[k], 0.f);
        AC[h] += a;
    }

    for (int i = threadIdx.x; i < 64 * Ct; i += 256) {
        int o = i / Ct, c = i - o * Ct;
        float s = fold ? sS[c] : 1.f;
        Ws1[o * ld2 + c] = __float2bfloat16_rn(W1[i] * s);
        Ws2[o * ld2 + c] = __float2bfloat16_rn(W2[i] * s);
    }
    if (threadIdx.x < 64) {
        int o = threadIdx.x;
        float a1 = b1[o], a2 = b2[o];
        if (fold)
            for (int c = 0; c < Ct; c++) {
                float t = sT[c];
                a1 += W1[o * Ct + c] * t;
                a2 += W2[o * Ct + c] * t;
            }
        bs1[o] = a1; bs2[o] = a2;
    }

    const int p0   = blockIdx.x * 128;
    const int lane = threadIdx.x & 31;
    const int wid  = threadIdx.x >> 5;
    const int cg = wid & 3, rg = wid >> 2;
    const int lq = lane & 3, lr = lane >> 2;
    const int lml = lane & 15, lmh = (lane >> 4) << 3;

    float acc1[2][4][4], acc2[2][4][4];
#pragma unroll
    for (int mi = 0; mi < 2; mi++)
#pragma unroll
        for (int nj = 0; nj < 4; nj++)
#pragma unroll
            for (int q = 0; q < 4; q++) { acc1[mi][nj][q] = 0.f; acc2[mi][nj][q] = 0.f; }

    for (int k0 = 0; k0 < Ct; k0 += 32) {
        __syncthreads();
        for (int i = threadIdx.x; i < 512; i += 256) {        // 32 rows x 128 bf16
            int kk = i >> 4, c8 = (i & 15) << 3;
            *(float4*)(Us + kk * 136 + c8) =
                *(const float4*)(in + (size_t)(k0 + kk) * NP + p0 + c8);
        }
        __syncthreads();
#pragma unroll
        for (int kk = 0; kk < 32; kk += 16) {
            uint32_t a1[2][4], a2[2][4], bq[2][4];
#pragma unroll
            for (int mi = 0; mi < 2; mi++) {
                int r = rg * 32 + mi * 16 + lml;
                LDSM4(a1[mi], smaddr(Ws1 + r * ld2 + k0 + kk + lmh));
                LDSM4(a2[mi], smaddr(Ws2 + r * ld2 + k0 + kk + lmh));
            }
#pragma unroll
            for (int njp = 0; njp < 2; njp++)
                LDSM4T(bq[njp], smaddr(Us + (kk + lml) * 136 + cg * 32 + njp * 16 + lmh));
#pragma unroll
            for (int mi = 0; mi < 2; mi++)
#pragma unroll
                for (int njp = 0; njp < 2; njp++) {
                    MMA_BF16(acc1[mi][2*njp],   a1[mi], (bq[njp]));
                    MMA_BF16(acc1[mi][2*njp+1], a1[mi], (bq[njp]+2));
                    MMA_BF16(acc2[mi][2*njp],   a2[mi], (bq[njp]));
                    MMA_BF16(acc2[mi][2*njp+1], a2[mi], (bq[njp]+2));
                }
        }
    }

#pragma unroll
    for (int mi = 0; mi < 2; mi++) {
        int o0 = rg * 32 + mi * 16 + lr, o1 = o0 + 8;
        float c10 = bs1[o0], c11 = bs1[o1], c20 = bs2[o0], c21 = bs2[o1];
#pragma unroll
        for (int nj = 0; nj < 4; nj++) {
            int col = p0 + cg * 32 + nj * 8 + 2 * lq;
            *(bf162*)(O1 + (size_t)o0 * NP + col) =
                __floats2bfloat162_rn(acc1[mi][nj][0] + c10, acc1[mi][nj][1] + c10);
            *(bf162*)(O1 + (size_t)o1 * NP + col) =
                __floats2bfloat162_rn(acc1[mi][nj][2] + c11, acc1[mi][nj][3] + c11);
            *(bf162*)(O2 + (size_t)o0 * NP + col) =
                __floats2bfloat162_rn(acc2[mi][nj][0] + c20, acc2[mi][nj][1] + c20);
            *(bf162*)(O2 + (size_t)o1 * NP + col) =
                __floats2bfloat162_rn(acc2[mi][nj][2] + c21, acc2[mi][nj][3] + c21);
        }
    }
}

// ---------------- batched 512^3 bf16 GEMM, cp.async double-buffered (R5) -----
#define LDA 72      // 144B row stride
#define LDB 136     // 272B row stride
#define STG (128*LDA + 64*LDB)   // bf16 elems per stage = 17920
__global__ __launch_bounds__(256) void k_mma(const bf16* __restrict__ A,
                                             const bf16* __restrict__ B,
                                             bf16* __restrict__ C,
                                             float* __restrict__ ST,
                                             const float* __restrict__ bng,
                                             const float* __restrict__ bnb,
                                             int fold) {
    extern __shared__ bf16 dsm[];                  // 2 stages
    const int ch = blockIdx.z;
    const bf16* Ab = A + (size_t)ch * NP;
    const bf16* Bb = B + (size_t)ch * NP;
    bf16*       Cb = C + (size_t)ch * NP;
    const int tid  = threadIdx.x;
    const int lane = tid & 31, wid = tid >> 5;
    const int wr = wid >> 1, wc = wid & 1;
    const int lq = lane & 3, lr = lane >> 2;
    const int lml = lane & 15, lmh = (lane >> 4) << 3;
    const int rowBase = blockIdx.y * 128;
    const int colBase = blockIdx.x * 128;

    float acc[2][8][4];
#pragma unroll
    for (int mi = 0; mi < 2; mi++)
#pragma unroll
        for (int nj = 0; nj < 8; nj++)
#pragma unroll
            for (int q = 0; q < 4; q++) acc[mi][nj][q] = 0.f;

    auto loadTile = [&](int t, int s) {
        bf16* As = dsm + s * STG;
        bf16* Bs = As + 128 * LDA;
        int k0 = t * 64;
#pragma unroll
        for (int i = 0; i < 4; i++) {              // A: 128 rows x 64 bf16
            int lin = tid + i * 256;
            int r = lin >> 3, kc = (lin & 7) << 3;
            cp16(As + r * LDA + kc, Ab + (size_t)(rowBase + r) * NN + k0 + kc);
        }
#pragma unroll
        for (int i = 0; i < 4; i++) {              // B: 64 rows x 128 bf16
            int lin = tid + i * 256;
            int kk = lin >> 4, c8 = (lin & 15) << 3;
            cp16(Bs + kk * LDB + c8, Bb + (size_t)(k0 + kk) * NN + colBase + c8);
        }
        asm volatile("cp.async.commit_group;");
    };

    loadTile(0, 0);

    // block (0,0,0): snapshot s,t for mix4, then reset raw accumulators
    if (blockIdx.x == 0 && blockIdx.y == 0 && blockIdx.z == 0) {
        if (fold && tid < 64) {
            int c = tid;
            float sum = ST[ST_SUM + c], sq = ST[ST_SQ + c];
            float m   = sum / (float)NP;
            float var = sq / (float)NP - m * m;
            float s   = bng[c] * rsqrtf(var + 1e-5f);
            ST[ST_S + c] = s; ST[ST_T + c] = bnb[c] - m * s;
        }
    }
    __syncthreads();
    if (blockIdx.x == 0 && blockIdx.y == 0 && blockIdx.z == 0 && tid < 192)
        ST[ST_SUM + tid] = 0.f;

    for (int t = 0; t < 8; t++) {                  // k-tiles of 64
        if (t < 7) {
            loadTile(t + 1, (t + 1) & 1);
            asm volatile("cp.async.wait_group 1;");
        } else {
            asm volatile("cp.async.wait_group 0;");
        }
        __syncthreads();
        const bf16* As = dsm + (t & 1) * STG;
        const bf16* Bs = As + 128 * LDA;
#pragma unroll
        for (int kk = 0; kk < 64; kk += 16) {
            uint32_t a[2][4], bq[4][4];
#pragma unroll
            for (int mi = 0; mi < 2; mi++) {
                int r = wr * 32 + mi * 16 + lml;
                LDSM4(a[mi], smaddr(As + r * LDA + kk + lmh));
            }
#pragma unroll
            for (int njp = 0; njp < 4; njp++)
                LDSM4T(bq[njp], smaddr(Bs + (kk + lml) * LDB + wc * 64 + njp * 16 + lmh));
#pragma unroll
            for (int mi = 0; mi < 2; mi++)
#pragma unroll
                for (int njp = 0; njp < 4; njp++) {
                    MMA_BF16(acc[mi][2*njp],   a[mi], (bq[njp]));
                    MMA_BF16(acc[mi][2*njp+1], a[mi], (bq[njp]+2));
                }
        }
        __syncthreads();
    }

#pragma unroll
    for (int mi = 0; mi < 2; mi++) {
        int r0 = rowBase + wr * 32 + mi * 16 + lr;
#pragma unroll
        for (int nj = 0; nj < 8; nj++) {
            int col = colBase + wc * 64 + nj * 8 + 2 * lq;
            *(bf162*)(Cb + (size_t)r0 * NN + col) =
                __floats2bfloat162_rn(acc[mi][nj][0], acc[mi][nj][1]);
            *(bf162*)(Cb + (size_t)(r0 + 8) * NN + col) =
                __floats2bfloat162_rn(acc[mi][nj][2], acc[mi][nj][3]);
        }
    }
}

// ---------------- mix4: concat(M, cur) -> out (bf16), stats epilogue ---------
__global__ __launch_bounds__(256) void k_mix4(
    const bf16* __restrict__ Mt, const bf16* __restrict__ cur, int C2,
    const float* __restrict__ W, const float* __restrict__ bias,
    int fold, bf16* __restrict__ out, float* __restrict__ ST) {
    const int Ct = 64 + C2;
    const int ld2 = Ct + 8;
    extern __shared__ char shraw[];
    bf16*  Ws = (bf16*)shraw;               // [64][ld2]
    float* bs = (float*)(Ws + 64 * ld2);    // 64
    bf16*  Us = (bf16*)(bs + 64);           // [32][136]
    float* sSum = (float*)(Us + 32 * 136);  // 64
    float* sSq  = sSum + 64;                // 64
    float* sTr  = sSq + 64;                 // 64

    for (int i = threadIdx.x; i < 64 * Ct; i += 256) {
        int o = i / Ct, c = i - o * Ct;
        float s = (c >= 64 && fold) ? ST[ST_S + c - 64] : 1.f;
        Ws[o * ld2 + c] = __float2bfloat16_rn(W[i] * s);
    }
    if (threadIdx.x < 64) {
        int o = threadIdx.x;
        float a = bias[o];
        if (fold)
            for (int c = 64; c < Ct; c++) a += W[o * Ct + c] * ST[ST_T + c - 64];
        bs[o] = a;
    }
    if (threadIdx.x < 192) sSum[threadIdx.x] = 0.f;   // zeros sum/sq/tr

    const int p0   = blockIdx.x * 128;
    const int lane = threadIdx.x & 31;
    const int wid  = threadIdx.x >> 5;
    const int cg = wid & 3, rg = wid >> 2;
    const int lq = lane & 3, lr = lane >> 2;
    const int lml = lane & 15, lmh = (lane >> 4) << 3;

    float acc[2][4][4];
#pragma unroll
    for (int mi = 0; mi < 2; mi++)
#pragma unroll
        for (int nj = 0; nj < 4; nj++)
#pragma unroll
            for (int q = 0; q < 4; q++) acc[mi][nj][q] = 0.f;

    for (int k0 = 0; k0 < Ct; k0 += 32) {
        __syncthreads();
        for (int i = threadIdx.x; i < 512; i += 256) {
            int kk = i >> 4, c8 = (i & 15) << 3;
            int c = k0 + kk;
            const bf16* src = (c < 64) ? Mt + (size_t)c * NP
                                       : cur + (size_t)(c - 64) * NP;
            *(float4*)(Us + kk * 136 + c8) = *(const float4*)(src + p0 + c8);
        }
        __syncthreads();
#pragma unroll
        for (int kk = 0; kk < 32; kk += 16) {
            uint32_t a[2][4], bq[2][4];
#pragma unroll
            for (int mi = 0; mi < 2; mi++) {
                int r = rg * 32 + mi * 16 + lml;
                LDSM4(a[mi], smaddr(Ws + r * ld2 + k0 + kk + lmh));
            }
#pragma unroll
            for (int njp = 0; njp < 2; njp++)
                LDSM4T(bq[njp], smaddr(Us + (kk + lml) * 136 + cg * 32 + njp * 16 + lmh));
#pragma unroll
            for (int mi = 0; mi < 2; mi++)
#pragma unroll
                for (int njp = 0; njp < 2; njp++) {
                    MMA_BF16(acc[mi][2*njp],   a[mi], (bq[njp]));
                    MMA_BF16(acc[mi][2*njp+1], a[mi], (bq[njp]+2));
                }
        }
    }
    __syncthreads();

    int dp = ((p0 + 512) / 513) * 513;          // diagonal column inside block
    bool hasDiag = (dp < p0 + 128);

#pragma unroll
    for (int mi = 0; mi < 2; mi++) {
        int o0 = rg * 32 + mi * 16 + lr, o1 = o0 + 8;
        float b0 = bs[o0], b1v = bs[o1];
        float s0 = 0.f, q0 = 0.f, s1 = 0.f, q1 = 0.f;
#pragma unroll
        for (int nj = 0; nj < 4; nj++) {
            int col = p0 + cg * 32 + nj * 8 + 2 * lq;
            float v00 = acc[mi][nj][0] + b0, v01 = acc[mi][nj][1] + b0;
            float v10 = acc[mi][nj][2] + b1v, v11 = acc[mi][nj][3] + b1v;
            if (out) {
                *(bf162*)(out + (size_t)o0 * NP + col) = __floats2bfloat162_rn(v00, v01);
                *(bf162*)(out + (size_t)o1 * NP + col) = __floats2bfloat162_rn(v10, v11);
            }
            s0 += v00 + v01; q0 += v00 * v00 + v01 * v01;
            s1 += v10 + v11; q1 += v10 * v10 + v11 * v11;
            if (hasDiag) {
                if (col == dp)     { atomicAdd(&sTr[o0], v00); atomicAdd(&sTr[o1], v10); }
                if (col + 1 == dp) { atomicAdd(&sTr[o0], v01); atomicAdd(&sTr[o1], v11); }
            }
        }
#pragma unroll
        for (int off = 1; off < 4; off <<= 1) {
            s0 += __shfl_xor_sync(0xffffffffu, s0, off);
            q0 += __shfl_xor_sync(0xffffffffu, q0, off);
            s1 += __shfl_xor_sync(0xffffffffu, s1, off);
            q1 += __shfl_xor_sync(0xffffffffu, q1, off);
        }
        if (lq == 0) {
            atomicAdd(&sSum[o0], s0); atomicAdd(&sSq[o0], q0);
            atomicAdd(&sSum[o1], s1); atomicAdd(&sSq[o1], q1);
        }
    }
    __syncthreads();
    if (threadIdx.x < 64) {
        int c = threadIdx.x;
        atomicAdd(&ST[ST_SUM + c], sSum[c]);
        atomicAdd(&ST[ST_SQ  + c], sSq[c]);
        if (sTr[c] != 0.f) atomicAdd(&ST[ST_TR + c], sTr[c]);
    }
}

// ---------------- head: layer-2 finalize + extractor + classifier ------------
__global__ void k_head(float* __restrict__ ST,
                       const float* __restrict__ g, const float* __restrict__ b,
                       const float* __restrict__ ew1, const float* __restrict__ eb1,
                       const float* __restrict__ ew2, const float* __restrict__ ew3,
                       const float* __restrict__ acc,
                       const float* __restrict__ ac_w, const float* __restrict__ ac_b,
                       const float* __restrict__ fl_w, const float* __restrict__ fl_b,
                       float* __restrict__ out) {
    __shared__ float o[64], t[64], osh[64], lg[10];
    int h = threadIdx.x;                               // 64 threads
    {
        float sum = ST[ST_SUM + h], sq = ST[ST_SQ + h], tr = ST[ST_TR + h];
        float m   = sum / (float)NP;
        float var = sq / (float)NP - m * m;
        float s   = g[h] * rsqrtf(var + 1e-5f);
        float tt  = b[h] - m * s;
        o[h] = tr * s + 512.f * tt;                    // str
        t[h] = sum * s + (float)NP * tt;               // stot
    }
    __syncthreads();
    float oo = eb1[h];
    for (int c = 0; c < 64; c++)
        oo += ew1[h * 64 + c] * (o[c] / 512.f)
            + ew2[h * 64 + c] * ((t[c] - o[c]) / (512.f * 511.f));
    osh[h] = oo;
    __syncthreads();
    float a = osh[h];
    for (int k = 0; k < 64; k++) a += ew3[h * 64 + k] * fmaxf(osh[k], 0.f);
    float accv = acc[h] + a;
    __syncthreads();
    o[h] = fmaxf(accv, 0.f) / (float)NL;
    __syncthreads();
    float s2 = ac_b[h];
    for (int k = 0; k < 64; k++) s2 += ac_w[h * 64 + k] * o[k];
    t[h] = o[h] + fmaxf(s2, 0.f);
    __syncthreads();
    if (h < 10) {
        float l = fl_b[h];
        for (int k = 0; k < 64; k++) l += fl_w[h * 64 + k] * t[k];
        lg[h] = l;
    }
    __syncthreads();
    if (h < 10) {
        float m = -1e30f;
        for (int i = 0; i < 10; i++) m = fmaxf(m, lg[i]);
        float se = 0.f;
        for (int i = 0; i < 10; i++) se += expf(lg[i] - m);
        out[h] = lg[h] - m - logf(se);
    }
}

// ---------------- launch -----------------------------------------------------
extern "C" void kernel_launch(void* const* d_in, const int* in_sizes, int n_in,
                              void* d_out, int out_size) {
    const float* x     = (const float*)d_in[0];
    const int*   ei    = (const int*)  d_in[1];
    const float* np1_w = (const float*)d_in[2];
    const float* np1_b = (const float*)d_in[3];
    const float* np2_w = (const float*)d_in[4];
    const float* np3_w = (const float*)d_in[5];
    const float* c0m1w = (const float*)d_in[6];
    const float* c0m1b = (const float*)d_in[7];
    const float* c0m2w = (const float*)d_in[8];
    const float* c0m2b = (const float*)d_in[9];
    const float* c0m4w = (const float*)d_in[10];
    const float* c0m4b = (const float*)d_in[11];
    const float* cm1w  = (const float*)d_in[12];
    const float* cm1b  = (const float*)d_in[13];
    const float* cm2w  = (const float*)d_in[14];
    const float* cm2b  = (const float*)d_in[15];
    const float* cm4w  = (const float*)d_in[16];
    const float* cm4b  = (const float*)d_in[17];
    const float* bn_g  = (const float*)d_in[18];
    const float* bn_b  = (const float*)d_in[19];
    const float* fe1w  = (const float*)d_in[20];
    const float* fe1b  = (const float*)d_in[21];
    const float* fe2w  = (const float*)d_in[22];
    const float* fe3w  = (const float*)d_in[23];
    const float* ac_w  = (const float*)d_in[24];
    const float* ac_b  = (const float*)d_in[25];
    const float* fl_w  = (const float*)d_in[26];
    const float* fl_b  = (const float*)d_in[27];

    float *ST, *AC;
    bf16 *Ub, *V0, *V1, *O1, *O2, *M;
    cudaGetSymbolAddress((void**)&Ub, g_Ub);
    cudaGetSymbolAddress((void**)&V0, g_V0);
    cudaGetSymbolAddress((void**)&V1, g_V1);
    cudaGetSymbolAddress((void**)&O1, g_O1);
    cudaGetSymbolAddress((void**)&O2, g_O2);
    cudaGetSymbolAddress((void**)&M,  g_M);
    cudaGetSymbolAddress((void**)&ST, g_ST);
    cudaGetSymbolAddress((void**)&AC, g_AC);

    static bool attr_done = false;
    if (!attr_done) {
        cudaFuncSetAttribute(k_mma,   cudaFuncAttributeMaxDynamicSharedMemorySize, 2 * STG * 2);
        cudaFuncSetAttribute(k_mixAB, cudaFuncAttributeMaxDynamicSharedMemorySize, 64 * 1024);
        cudaFuncSetAttribute(k_mix4,  cudaFuncAttributeMaxDynamicSharedMemorySize, 64 * 1024);
        attr_done = true;
    }

    k_zero<<<(16u * NP) / 256, 256>>>((uint32_t*)Ub, AC, ST);
    k_scatter<<<(EE * 32) / 256, 256>>>(x, ei, Ub);
    k_ext_stats<<<TWOF, 256>>>(Ub, ST + ST_ATR);

    const bf16* cur = Ub;
    for (int l = 0; l < NL; l++) {
        const int Cin = l ? 64 : TWOF;
        const int fold = (l > 0) ? 1 : 0;
        const float* m1w = l ? cm1w + (l - 1) * 64 * 64  : c0m1w;
        const float* m1b = l ? cm1b + (l - 1) * 64       : c0m1b;
        const float* m2w = l ? cm2w + (l - 1) * 64 * 64  : c0m2w;
        const float* m2b = l ? cm2b + (l - 1) * 64       : c0m2b;
        const float* m4w = l ? cm4w + (l - 1) * 64 * 128 : c0m4w;
        const float* m4b = l ? cm4b + (l - 1) * 64       : c0m4b;
        const float* pbg = l ? bn_g + 64 * (l - 1) : nullptr;  // prev-layer bn
        const float* pbb = l ? bn_b + 64 * (l - 1) : nullptr;
        // extractor to flush: layer 0 -> adjacency (np), else fe of layer l-1
        const float* sta = l ? nullptr : (ST + ST_ATR);
        const float* ew1 = l ? fe1w + (l - 1) * 64 * 64 : np1_w;
        const float* eb1 = l ? fe1b + (l - 1) * 64      : np1_b;
        const float* ew2 = l ? fe2w + (l - 1) * 64 * 64 : np2_w;
        const float* ew3 = l ? fe3w + (l - 1) * 64 * 64 : np3_w;
        const int    eC  = l ? 64 : TWOF;

        int ldab = Cin + 8;
        size_t shAB = (size_t)(2 * 64 * ldab + 32 * 136) * 2 + 2 * 64 * 4;
        k_mixAB<<<2048, 256, shAB>>>(cur, Cin, m1w, m1b, m2w, m2b, ST, fold,
                                     pbg, pbb, sta, ew1, eb1, ew2, ew3, eC, AC,
                                     O1, O2);

        k_mma<<<dim3(4, 4, 64), 256, 2 * STG * 2>>>(O1, O2, M, ST, pbg, pbb, fold);

        bf16* nxt = (l == 0) ? V0 : ((l == 1) ? V1 : nullptr);
        int ld4 = 64 + Cin + 8;
        size_t sh4 = (size_t)(64 * ld4 + 32 * 136) * 2 + (64 + 192) * 4;
        k_mix4<<<2048, 256, sh4>>>(M, cur, Cin, m4w, m4b, fold, nxt, ST);

        cur = nxt;
    }

    k_head<<<1, 64>>>(ST, bn_g + 128, bn_b + 128,
                      fe1w + 2 * 64 * 64, fe1b + 2 * 64,
                      fe2w + 2 * 64 * 64, fe3w + 2 * 64 * 64,
                      AC, ac_w, ac_b, fl_w, fl_b, (float*)d_out);
}

// round 12
// speedup vs baseline: 1.2510x; 1.0794x over previous
#include <cuda_runtime.h>
#include <cuda_bf16.h>
#include <math.h>
#include <stdint.h>

#define NN   512
#define NP   (NN*NN)        // 262144
#define FIN  16
#define TWOF 32
#define EE   16384
#define NL   3

// g_ST layout
#define ST_SUM   0
#define ST_SQ    64
#define ST_TR    128
#define ST_S     192
#define ST_T     256
#define ST_ATR   320

typedef __nv_bfloat16 bf16;
typedef __nv_bfloat162 bf162;

// ---------------- scratch (device globals; no allocation allowed) ----------
__device__ bf16  g_Ub[32u*NP];        // bf16 adjacency (scatter target)
__device__ bf16  g_V0[64u*NP];
__device__ bf16  g_V1[64u*NP];
__device__ bf16  g_O1[64u*NP];
__device__ bf16  g_O2[64u*NP];
__device__ bf16  g_M [64u*NP];
__device__ float g_ST[448];
__device__ float g_AC[64];

#define MMA_BF16(d, a, b)                                                      \
    asm volatile(                                                              \
        "mma.sync.aligned.m16n8k16.row.col.f32.bf16.bf16.f32 "                 \
        "{%0,%1,%2,%3},{%4,%5,%6,%7},{%8,%9},{%0,%1,%2,%3};"                   \
        : "+f"(d[0]), "+f"(d[1]), "+f"(d[2]), "+f"(d[3])                       \
        : "r"(a[0]), "r"(a[1]), "r"(a[2]), "r"(a[3]), "r"(b[0]), "r"(b[1]))

#define LDSM4(R, addr)                                                         \
    asm volatile("ldmatrix.sync.aligned.m8n8.x4.shared.b16 {%0,%1,%2,%3},[%4];"\
        : "=r"(R[0]), "=r"(R[1]), "=r"(R[2]), "=r"(R[3]) : "r"(addr))

#define LDSM4T(R, addr)                                                        \
    asm volatile("ldmatrix.sync.aligned.m8n8.x4.trans.shared.b16 {%0,%1,%2,%3},[%4];"\
        : "=r"(R[0]), "=r"(R[1]), "=r"(R[2]), "=r"(R[3]) : "r"(addr))

__device__ __forceinline__ uint32_t smaddr(const void* p) {
    return (uint32_t)__cvta_generic_to_shared(p);
}
__device__ __forceinline__ void cp16(void* smem, const void* g) {
    asm volatile("cp.async.cg.shared.global [%0], [%1], 16;"
                 :: "r"(smaddr(smem)), "l"(g));
}

// ---------------- init: zero bf16 adjacency + AC + ST ------------------------
__global__ void k_zero(uint4* Ub16, float* AC, float* ST) {
    int i = blockIdx.x * 256 + threadIdx.x;           // 4*NP uint4 words
    Ub16[i] = make_uint4(0u, 0u, 0u, 0u);
    if (i < 64)  AC[i] = 0.f;
    if (i < 448) ST[i] = 0.f;
}

// ---------------- scatter edges into A[c][src][dst] (bf16 atomics) -----------
__global__ void k_scatter(const float* __restrict__ x, const int* __restrict__ ei,
                          bf16* __restrict__ A) {
    int t = blockIdx.x * 256 + threadIdx.x;           // EE*32 threads
    int e = t >> 5, c = t & 31;
    int s = ei[e], d = ei[EE + e];
    float v = (c < FIN) ? x[s * FIN + c] : x[d * FIN + (c - FIN)];
    atomicAdd(&A[(size_t)c * NP + s * NN + d], __float2bfloat16_rn(v));
}

// ---------------- per-channel trace + total of A (bf16 in, fp32 reduce) ------
__global__ void k_ext_stats(const bf16* __restrict__ U, float* __restrict__ st) {
    int c = blockIdx.x;
    const bf16* u = U + (size_t)c * NP;
    const uint4* u8 = (const uint4*)u;                // 8 bf16 per uint4
    float tot = 0.f, tr = 0.f;
    for (int i = threadIdx.x; i < NP / 8; i += 256) {
        uint4 v = u8[i];
        float2 f0 = __bfloat1622float2(*(bf162*)&v.x);
        float2 f1 = __bfloat1622float2(*(bf162*)&v.y);
        float2 f2 = __bfloat1622float2(*(bf162*)&v.z);
        float2 f3 = __bfloat1622float2(*(bf162*)&v.w);
        tot += (f0.x + f0.y) + (f1.x + f1.y) + (f2.x + f2.y) + (f3.x + f3.y);
    }
    for (int i = threadIdx.x; i < NN; i += 256) tr += __bfloat162float(u[i * (NN + 1)]);
    __shared__ float s1[256], s2[256];
    s1[threadIdx.x] = tot; s2[threadIdx.x] = tr; __syncthreads();
    for (int o = 128; o > 0; o >>= 1) {
        if (threadIdx.x < o) { s1[threadIdx.x] += s1[threadIdx.x+o]; s2[threadIdx.x] += s2[threadIdx.x+o]; }
        __syncthreads();
    }
    if (threadIdx.x == 0) { st[c] = s2[0]; st[64 + c] = s1[0]; }
}

// ---------------- fused mix1+mix2 (+ BN fold + prev-layer extractor flush) ---
__global__ __launch_bounds__(256) void k_mixAB(
    const bf16* __restrict__ in, int Ct,
    const float* __restrict__ W1, const float* __restrict__ b1,
    const float* __restrict__ W2, const float* __restrict__ b2,
    const float* __restrict__ ST, int fold,
    const float* __restrict__ bng, const float* __restrict__ bnb,
    const float* __restrict__ STA,       // adjacency stats (layer 0) or null
    const float* __restrict__ ew1, const float* __restrict__ eb1,
    const float* __restrict__ ew2, const float* __restrict__ ew3, int eC,
    float* __restrict__ AC,
    bf16* __restrict__ O1, bf16* __restrict__ O2) {
    const int ld2 = Ct + 8;                 // row stride: (Ct+8)*2B = 16*odd
    extern __shared__ char shraw[];
    bf16*  Ws1 = (bf16*)shraw;              // [64][ld2]
    bf16*  Ws2 = Ws1 + 64 * ld2;
    float* bs1 = (float*)(Ws2 + 64 * ld2);
    float* bs2 = bs1 + 64;
    bf16*  Us  = (bf16*)(bs2 + 64);         // [32][136]
    __shared__ float sS[64], sT[64], osh[64];

    // per-block BN params from raw stats (finalize folded in)
    if (fold && threadIdx.x < 64) {
        int c = threadIdx.x;
        float sum = ST[ST_SUM + c], sq = ST[ST_SQ + c];
        float m   = sum / (float)NP;
        float var = sq / (float)NP - m * m;
        float s   = bng[c] * rsqrtf(var + 1e-5f);
        sS[c] = s; sT[c] = bnb[c] - m * s;
    }
    __syncthreads();

    // block 0: flush previous stage's extractor into AC
    if (blockIdx.x == 0 && threadIdx.x < 64) {
        int h = threadIdx.x;
        float o = eb1[h];
        for (int c = 0; c < eC; c++) {
            float str, stot;
            if (STA) { str = STA[c]; stot = STA[64 + c]; }
            else {
                float s = sS[c], t = sT[c];
                str  = ST[ST_TR  + c] * s + 512.f * t;
                stot = ST[ST_SUM + c] * s + (float)NP * t;
            }
            o += ew1[h * eC + c] * (str / 512.f)
               + ew2[h * eC + c] * ((stot - str) / (512.f * 511.f));
        }
        osh[h] = o;
    }
    __syncthreads();
    if (blockIdx.x == 0 && threadIdx.x < 64) {
        int h = threadIdx.x;
        float a = osh[h];
        for (int k = 0; k < 64; k++) a += ew3[h * 64 + k] * fmaxf(osh[k], 0.f);
        AC[h] += a;
    }

    for (int i = threadIdx.x; i < 64 * Ct; i += 256) {
        int o = i / Ct, c = i - o * Ct;
        float s = fold ? sS[c] : 1.f;
        Ws1[o * ld2 + c] = __float2bfloat16_rn(W1[i] * s);
        Ws2[o * ld2 + c] = __float2bfloat16_rn(W2[i] * s);
    }
    if (threadIdx.x < 64) {
        int o = threadIdx.x;
        float a1 = b1[o], a2 = b2[o];
        if (fold)
            for (int c = 0; c < Ct; c++) {
                float t = sT[c];
                a1 += W1[o * Ct + c] * t;
                a2 += W2[o * Ct + c] * t;
            }
        bs1[o] = a1; bs2[o] = a2;
    }

    const int p0   = blockIdx.x * 128;
    const int lane = threadIdx.x & 31;
    const int wid  = threadIdx.x >> 5;
    const int cg = wid & 3, rg = wid >> 2;
    const int lq = lane & 3, lr = lane >> 2;
    const int lml = lane & 15, lmh = (lane >> 4) << 3;

    float acc1[2][4][4], acc2[2][4][4];
#pragma unroll
    for (int mi = 0; mi < 2; mi++)
#pragma unroll
        for (int nj = 0; nj < 4; nj++)
#pragma unroll
            for (int q = 0; q < 4; q++) { acc1[mi][nj][q] = 0.f; acc2[mi][nj][q] = 0.f; }

    for (int k0 = 0; k0 < Ct; k0 += 32) {
        __syncthreads();
        for (int i = threadIdx.x; i < 512; i += 256) {        // 32 rows x 128 bf16
            int kk = i >> 4, c8 = (i & 15) << 3;
            cp16(Us + kk * 136 + c8, in + (size_t)(k0 + kk) * NP + p0 + c8);
        }
        asm volatile("cp.async.commit_group;");
        asm volatile("cp.async.wait_group 0;");
        __syncthreads();
#pragma unroll
        for (int kk = 0; kk < 32; kk += 16) {
            uint32_t a1[2][4], a2[2][4], bq[2][4];
#pragma unroll
            for (int mi = 0; mi < 2; mi++) {
                int r = rg * 32 + mi * 16 + lml;
                LDSM4(a1[mi], smaddr(Ws1 + r * ld2 + k0 + kk + lmh));
                LDSM4(a2[mi], smaddr(Ws2 + r * ld2 + k0 + kk + lmh));
            }
#pragma unroll
            for (int njp = 0; njp < 2; njp++)
                LDSM4T(bq[njp], smaddr(Us + (kk + lml) * 136 + cg * 32 + njp * 16 + lmh));
#pragma unroll
            for (int mi = 0; mi < 2; mi++)
#pragma unroll
                for (int njp = 0; njp < 2; njp++) {
                    MMA_BF16(acc1[mi][2*njp],   a1[mi], (bq[njp]));
                    MMA_BF16(acc1[mi][2*njp+1], a1[mi], (bq[njp]+2));
                    MMA_BF16(acc2[mi][2*njp],   a2[mi], (bq[njp]));
                    MMA_BF16(acc2[mi][2*njp+1], a2[mi], (bq[njp]+2));
                }
        }
    }

    // biases into regs BEFORE staging buffer aliases bs1/bs2
    float bb1[2][2], bb2[2][2];
#pragma unroll
    for (int mi = 0; mi < 2; mi++) {
        int o0 = rg * 32 + mi * 16 + lr;
        bb1[mi][0] = bs1[o0]; bb1[mi][1] = bs1[o0 + 8];
        bb2[mi][0] = bs2[o0]; bb2[mi][1] = bs2[o0 + 8];
    }
    __syncthreads();

    // coalesced epilogue via smem staging: [64][136] bf16
    bf16* Os = (bf16*)shraw;
#pragma unroll
    for (int mi = 0; mi < 2; mi++) {
        int o0 = rg * 32 + mi * 16 + lr, o1 = o0 + 8;
#pragma unroll
        for (int nj = 0; nj < 4; nj++) {
            int col = cg * 32 + nj * 8 + 2 * lq;
            *(bf162*)(Os + o0 * 136 + col) =
                __floats2bfloat162_rn(acc1[mi][nj][0] + bb1[mi][0], acc1[mi][nj][1] + bb1[mi][0]);
            *(bf162*)(Os + o1 * 136 + col) =
                __floats2bfloat162_rn(acc1[mi][nj][2] + bb1[mi][1], acc1[mi][nj][3] + bb1[mi][1]);
        }
    }
    __syncthreads();
    for (int i = threadIdx.x * 8; i < 64 * 128; i += 2048) {
        int o = i >> 7, c = i & 127;
        *(float4*)(O1 + (size_t)o * NP + p0 + c) = *(float4*)(Os + o * 136 + c);
    }
    __syncthreads();
#pragma unroll
    for (int mi = 0; mi < 2; mi++) {
        int o0 = rg * 32 + mi * 16 + lr, o1 = o0 + 8;
#pragma unroll
        for (int nj = 0; nj < 4; nj++) {
            int col = cg * 32 + nj * 8 + 2 * lq;
            *(bf162*)(Os + o0 * 136 + col) =
                __floats2bfloat162_rn(acc2[mi][nj][0] + bb2[mi][0], acc2[mi][nj][1] + bb2[mi][0]);
            *(bf162*)(Os + o1 * 136 + col) =
                __floats2bfloat162_rn(acc2[mi][nj][2] + bb2[mi][1], acc2[mi][nj][3] + bb2[mi][1]);
        }
    }
    __syncthreads();
    for (int i = threadIdx.x * 8; i < 64 * 128; i += 2048) {
        int o = i >> 7, c = i & 127;
        *(float4*)(O2 + (size_t)o * NP + p0 + c) = *(float4*)(Os + o * 136 + c);
    }
}

// ---------------- batched 512^3 bf16 GEMM, cp.async double-buffered ----------
#define LDA 72      // 144B row stride
#define LDB 136     // 272B row stride
#define STG (128*LDA + 64*LDB)   // bf16 elems per stage = 17920
__global__ __launch_bounds__(256) void k_mma(const bf16* __restrict__ A,
                                             const bf16* __restrict__ B,
                                             bf16* __restrict__ C,
                                             float* __restrict__ ST,
                                             const float* __restrict__ bng,
                                             const float* __restrict__ bnb,
                                             int fold) {
    extern __shared__ bf16 dsm[];                  // 2 stages
    const int ch = blockIdx.z;
    const bf16* Ab = A + (size_t)ch * NP;
    const bf16* Bb = B + (size_t)ch * NP;
    bf16*       Cb = C + (size_t)ch * NP;
    const int tid  = threadIdx.x;
    const int lane = tid & 31, wid = tid >> 5;
    const int wr = wid >> 1, wc = wid & 1;
    const int lq = lane & 3, lr = lane >> 2;
    const int lml = lane & 15, lmh = (lane >> 4) << 3;
    const int rowBase = blockIdx.y * 128;
    const int colBase = blockIdx.x * 128;

    float acc[2][8][4];
#pragma unroll
    for (int mi = 0; mi < 2; mi++)
#pragma unroll
        for (int nj = 0; nj < 8; nj++)
#pragma unroll
            for (int q = 0; q < 4; q++) acc[mi][nj][q] = 0.f;

    auto loadTile = [&](int t, int s) {
        bf16* As = dsm + s * STG;
        bf16* Bs = As + 128 * LDA;
        int k0 = t * 64;
#pragma unroll
        for (int i = 0; i < 4; i++) {              // A: 128 rows x 64 bf16
            int lin = tid + i * 256;
            int r = lin >> 3, kc = (lin & 7) << 3;
            cp16(As + r * LDA + kc, Ab + (size_t)(rowBase + r) * NN + k0 + kc);
        }
#pragma unroll
        for (int i = 0; i < 4; i++) {              // B: 64 rows x 128 bf16
            int lin = tid + i * 256;
            int kk = lin >> 4, c8 = (lin & 15) << 3;
            cp16(Bs + kk * LDB + c8, Bb + (size_t)(k0 + kk) * NN + colBase + c8);
        }
        asm volatile("cp.async.commit_group;");
    };

    loadTile(0, 0);

    // block (0,0,0): snapshot s,t for mix4, then reset raw accumulators
    if (blockIdx.x == 0 && blockIdx.y == 0 && blockIdx.z == 0) {
        if (fold && tid < 64) {
            int c = tid;
            float sum = ST[ST_SUM + c], sq = ST[ST_SQ + c];
            float m   = sum / (float)NP;
            float var = sq / (float)NP - m * m;
            float s   = bng[c] * rsqrtf(var + 1e-5f);
            ST[ST_S + c] = s; ST[ST_T + c] = bnb[c] - m * s;
        }
    }
    __syncthreads();
    if (blockIdx.x == 0 && blockIdx.y == 0 && blockIdx.z == 0 && tid < 192)
        ST[ST_SUM + tid] = 0.f;

    for (int t = 0; t < 8; t++) {                  // k-tiles of 64
        if (t < 7) {
            loadTile(t + 1, (t + 1) & 1);
            asm volatile("cp.async.wait_group 1;");
        } else {
            asm volatile("cp.async.wait_group 0;");
        }
        __syncthreads();
        const bf16* As = dsm + (t & 1) * STG;
        const bf16* Bs = As + 128 * LDA;
#pragma unroll
        for (int kk = 0; kk < 64; kk += 16) {
            uint32_t a[2][4], bq[4][4];
#pragma unroll
            for (int mi = 0; mi < 2; mi++) {
                int r = wr * 32 + mi * 16 + lml;
                LDSM4(a[mi], smaddr(As + r * LDA + kk + lmh));
            }
#pragma unroll
            for (int njp = 0; njp < 4; njp++)
                LDSM4T(bq[njp], smaddr(Bs + (kk + lml) * LDB + wc * 64 + njp * 16 + lmh));
#pragma unroll
            for (int mi = 0; mi < 2; mi++)
#pragma unroll
                for (int njp = 0; njp < 4; njp++) {
                    MMA_BF16(acc[mi][2*njp],   a[mi], (bq[njp]));
                    MMA_BF16(acc[mi][2*njp+1], a[mi], (bq[njp]+2));
                }
        }
        __syncthreads();
    }

    // coalesced epilogue: stage 128x128 tile in smem (row stride 136)
    bf16* Cs = dsm;
#pragma unroll
    for (int mi = 0; mi < 2; mi++) {
        int r0 = wr * 32 + mi * 16 + lr;
#pragma unroll
        for (int nj = 0; nj < 8; nj++) {
            int col = wc * 64 + nj * 8 + 2 * lq;
            *(bf162*)(Cs + r0 * 136 + col) =
                __floats2bfloat162_rn(acc[mi][nj][0], acc[mi][nj][1]);
            *(bf162*)(Cs + (r0 + 8) * 136 + col) =
                __floats2bfloat162_rn(acc[mi][nj][2], acc[mi][nj][3]);
        }
    }
    __syncthreads();
    for (int i = tid * 8; i < 128 * 128; i += 2048) {
        int r = i >> 7, c = i & 127;
        *(float4*)(Cb + (size_t)(rowBase + r) * NN + colBase + c) =
            *(float4*)(Cs + r * 136 + c);
    }
}

// ---------------- mix4: concat(M, cur) -> out (bf16), stats epilogue ---------
__global__ __launch_bounds__(256) void k_mix4(
    const bf16* __restrict__ Mt, const bf16* __restrict__ cur, int C2,
    const float* __restrict__ W, const float* __restrict__ bias,
    int fold, bf16* __restrict__ out, float* __restrict__ ST) {
    const int Ct = 64 + C2;
    const int ld2 = Ct + 8;
    extern __shared__ char shraw[];
    bf16*  Ws = (bf16*)shraw;               // [64][ld2]
    float* bs = (float*)(Ws + 64 * ld2);    // 64
    bf16*  Us = (bf16*)(bs + 64);           // [32][136]
    float* sSum = (float*)(Us + 32 * 136);  // 64
    float* sSq  = sSum + 64;                // 64
    float* sTr  = sSq + 64;                 // 64

    for (int i = threadIdx.x; i < 64 * Ct; i += 256) {
        int o = i / Ct, c = i - o * Ct;
        float s = (c >= 64 && fold) ? ST[ST_S + c - 64] : 1.f;
        Ws[o * ld2 + c] = __float2bfloat16_rn(W[i] * s);
    }
    if (threadIdx.x < 64) {
        int o = threadIdx.x;
        float a = bias[o];
        if (fold)
            for (int c = 64; c < Ct; c++) a += W[o * Ct + c] * ST[ST_T + c - 64];
        bs[o] = a;
    }
    if (threadIdx.x < 192) sSum[threadIdx.x] = 0.f;   // zeros sum/sq/tr

    const int p0   = blockIdx.x * 128;
    const int lane = threadIdx.x & 31;
    const int wid  = threadIdx.x >> 5;
    const int cg = wid & 3, rg = wid >> 2;
    const int lq = lane & 3, lr = lane >> 2;
    const int lml = lane & 15, lmh = (lane >> 4) << 3;

    float acc[2][4][4];
#pragma unroll
    for (int mi = 0; mi < 2; mi++)
#pragma unroll
        for (int nj = 0; nj < 4; nj++)
#pragma unroll
            for (int q = 0; q < 4; q++) acc[mi][nj][q] = 0.f;

    for (int k0 = 0; k0 < Ct; k0 += 32) {
        __syncthreads();
        for (int i = threadIdx.x; i < 512; i += 256) {
            int kk = i >> 4, c8 = (i & 15) << 3;
            int c = k0 + kk;
            const bf16* src = (c < 64) ? Mt + (size_t)c * NP
                                       : cur + (size_t)(c - 64) * NP;
            cp16(Us + kk * 136 + c8, src + p0 + c8);
        }
        asm volatile("cp.async.commit_group;");
        asm volatile("cp.async.wait_group 0;");
        __syncthreads();
#pragma unroll
        for (int kk = 0; kk < 32; kk += 16) {
            uint32_t a[2][4], bq[2][4];
#pragma unroll
            for (int mi = 0; mi < 2; mi++) {
                int r = rg * 32 + mi * 16 + lml;
                LDSM4(a[mi], smaddr(Ws + r * ld2 + k0 + kk + lmh));
            }
#pragma unroll
            for (int njp = 0; njp < 2; njp++)
                LDSM4T(bq[njp], smaddr(Us + (kk + lml) * 136 + cg * 32 + njp * 16 + lmh));
#pragma unroll
            for (int mi = 0; mi < 2; mi++)
#pragma unroll
                for (int njp = 0; njp < 2; njp++) {
                    MMA_BF16(acc[mi][2*njp],   a[mi], (bq[njp]));
                    MMA_BF16(acc[mi][2*njp+1], a[mi], (bq[njp]+2));
                }
        }
    }

    // biases into regs BEFORE staging overwrites bs
    float bb[2][2];
#pragma unroll
    for (int mi = 0; mi < 2; mi++) {
        int o0 = rg * 32 + mi * 16 + lr;
        bb[mi][0] = bs[o0]; bb[mi][1] = bs[o0 + 8];
    }
    __syncthreads();

    int dp = ((p0 + 512) / 513) * 513;          // diagonal column inside block
    bool hasDiag = (dp < p0 + 128);
    bf16* Os = (bf16*)shraw;                    // [64][136] staging (aliases Ws/Us)

#pragma unroll
    for (int mi = 0; mi < 2; mi++) {
        int o0 = rg * 32 + mi * 16 + lr, o1 = o0 + 8;
        float b0 = bb[mi][0], b1v = bb[mi][1];
        float s0 = 0.f, q0 = 0.f, s1 = 0.f, q1 = 0.f;
#pragma unroll
        for (int nj = 0; nj < 4; nj++) {
            int col = cg * 32 + nj * 8 + 2 * lq;
            float v00 = acc[mi][nj][0] + b0, v01 = acc[mi][nj][1] + b0;
            float v10 = acc[mi][nj][2] + b1v, v11 = acc[mi][nj][3] + b1v;
            *(bf162*)(Os + o0 * 136 + col) = __floats2bfloat162_rn(v00, v01);
            *(bf162*)(Os + o1 * 136 + col) = __floats2bfloat162_rn(v10, v11);
            s0 += v00 + v01; q0 += v00 * v00 + v01 * v01;
            s1 += v10 + v11; q1 += v10 * v10 + v11 * v11;
            if (hasDiag) {
                int gcol = p0 + col;
                if (gcol == dp)     { atomicAdd(&sTr[o0], v00); atomicAdd(&sTr[o1], v10); }
                if (gcol + 1 == dp) { atomicAdd(&sTr[o0], v01); atomicAdd(&sTr[o1], v11); }
            }
        }
#pragma unroll
        for (int off = 1; off < 4; off <<= 1) {
            s0 += __shfl_xor_sync(0xffffffffu, s0, off);
            q0 += __shfl_xor_sync(0xffffffffu, q0, off);
            s1 += __shfl_xor_sync(0xffffffffu, s1, off);
            q1 += __shfl_xor_sync(0xffffffffu, q1, off);
        }
        if (lq == 0) {
            atomicAdd(&sSum[o0], s0); atomicAdd(&sSq[o0], q0);
            atomicAdd(&sSum[o1], s1); atomicAdd(&sSq[o1], q1);
        }
    }
    __syncthreads();
    if (out) {
        for (int i = threadIdx.x * 8; i < 64 * 128; i += 2048) {
            int o = i >> 7, c = i & 127;
            *(float4*)(out + (size_t)o * NP + p0 + c) = *(float4*)(Os + o * 136 + c);
        }
    }
    if (threadIdx.x < 64) {
        int c = threadIdx.x;
        atomicAdd(&ST[ST_SUM + c], sSum[c]);
        atomicAdd(&ST[ST_SQ  + c], sSq[c]);
        if (sTr[c] != 0.f) atomicAdd(&ST[ST_TR + c], sTr[c]);
    }
}

// ---------------- head: layer-2 finalize + extractor + classifier ------------
__global__ void k_head(float* __restrict__ ST,
                       const float* __restrict__ g, const float* __restrict__ b,
                       const float* __restrict__ ew1, const float* __restrict__ eb1,
                       const float* __restrict__ ew2, const float* __restrict__ ew3,
                       const float* __restrict__ acc,
                       const float* __restrict__ ac_w, const float* __restrict__ ac_b,
                       const float* __restrict__ fl_w, const float* __restrict__ fl_b,
                       float* __restrict__ out) {
    __shared__ float o[64], t[64], osh[64], lg[10];
    int h = threadIdx.x;                               // 64 threads
    {
        float sum = ST[ST_SUM + h], sq = ST[ST_SQ + h], tr = ST[ST_TR + h];
        float m   = sum / (float)NP;
        float var = sq / (float)NP - m * m;
        float s   = g[h] * rsqrtf(var + 1e-5f);
        float tt  = b[h] - m * s;
        o[h] = tr * s + 512.f * tt;                    // str
        t[h] = sum * s + (float)NP * tt;               // stot
    }
    __syncthreads();
    float oo = eb1[h];
    for (int c = 0; c < 64; c++)
        oo += ew1[h * 64 + c] * (o[c] / 512.f)
            + ew2[h * 64 + c] * ((t[c] - o[c]) / (512.f * 511.f));
    osh[h] = oo;
    __syncthreads();
    float a = osh[h];
    for (int k = 0; k < 64; k++) a += ew3[h * 64 + k] * fmaxf(osh[k], 0.f);
    float accv = acc[h] + a;
    __syncthreads();
    o[h] = fmaxf(accv, 0.f) / (float)NL;
    __syncthreads();
    float s2 = ac_b[h];
    for (int k = 0; k < 64; k++) s2 += ac_w[h * 64 + k] * o[k];
    t[h] = o[h] + fmaxf(s2, 0.f);
    __syncthreads();
    if (h < 10) {
        float l = fl_b[h];
        for (int k = 0; k < 64; k++) l += fl_w[h * 64 + k] * t[k];
        lg[h] = l;
    }
    __syncthreads();
    if (h < 10) {
        float m = -1e30f;
        for (int i = 0; i < 10; i++) m = fmaxf(m, lg[i]);
        float se = 0.f;
        for (int i = 0; i < 10; i++) se += expf(lg[i] - m);
        out[h] = lg[h] - m - logf(se);
    }
}

// ---------------- launch -----------------------------------------------------
extern "C" void kernel_launch(void* const* d_in, const int* in_sizes, int n_in,
                              void* d_out, int out_size) {
    const float* x     = (const float*)d_in[0];
    const int*   ei    = (const int*)  d_in[1];
    const float* np1_w = (const float*)d_in[2];
    const float* np1_b = (const float*)d_in[3];
    const float* np2_w = (const float*)d_in[4];
    const float* np3_w = (const float*)d_in[5];
    const float* c0m1w = (const float*)d_in[6];
    const float* c0m1b = (const float*)d_in[7];
    const float* c0m2w = (const float*)d_in[8];
    const float* c0m2b = (const float*)d_in[9];
    const float* c0m4w = (const float*)d_in[10];
    const float* c0m4b = (const float*)d_in[11];
    const float* cm1w  = (const float*)d_in[12];
    const float* cm1b  = (const float*)d_in[13];
    const float* cm2w  = (const float*)d_in[14];
    const float* cm2b  = (const float*)d_in[15];
    const float* cm4w  = (const float*)d_in[16];
    const float* cm4b  = (const float*)d_in[17];
    const float* bn_g  = (const float*)d_in[18];
    const float* bn_b  = (const float*)d_in[19];
    const float* fe1w  = (const float*)d_in[20];
    const float* fe1b  = (const float*)d_in[21];
    const float* fe2w  = (const float*)d_in[22];
    const float* fe3w  = (const float*)d_in[23];
    const float* ac_w  = (const float*)d_in[24];
    const float* ac_b  = (const float*)d_in[25];
    const float* fl_w  = (const float*)d_in[26];
    const float* fl_b  = (const float*)d_in[27];

    float *ST, *AC;
    bf16 *Ub, *V0, *V1, *O1, *O2, *M;
    cudaGetSymbolAddress((void**)&Ub, g_Ub);
    cudaGetSymbolAddress((void**)&V0, g_V0);
    cudaGetSymbolAddress((void**)&V1, g_V1);
    cudaGetSymbolAddress((void**)&O1, g_O1);
    cudaGetSymbolAddress((void**)&O2, g_O2);
    cudaGetSymbolAddress((void**)&M,  g_M);
    cudaGetSymbolAddress((void**)&ST, g_ST);
    cudaGetSymbolAddress((void**)&AC, g_AC);

    static bool attr_done = false;
    if (!attr_done) {
        cudaFuncSetAttribute(k_mma,   cudaFuncAttributeMaxDynamicSharedMemorySize, 2 * STG * 2);
        cudaFuncSetAttribute(k_mixAB, cudaFuncAttributeMaxDynamicSharedMemorySize, 64 * 1024);
        cudaFuncSetAttribute(k_mix4,  cudaFuncAttributeMaxDynamicSharedMemorySize, 64 * 1024);
        attr_done = true;
    }

    k_zero<<<(4u * NP) / 256, 256>>>((uint4*)Ub, AC, ST);
    k_scatter<<<(EE * 32) / 256, 256>>>(x, ei, Ub);
    k_ext_stats<<<TWOF, 256>>>(Ub, ST + ST_ATR);

    const bf16* cur = Ub;
    for (int l = 0; l < NL; l++) {
        const int Cin = l ? 64 : TWOF;
        const int fold = (l > 0) ? 1 : 0;
        const float* m1w = l ? cm1w + (l - 1) * 64 * 64  : c0m1w;
        const float* m1b = l ? cm1b + (l - 1) * 64       : c0m1b;
        const float* m2w = l ? cm2w + (l - 1) * 64 * 64  : c0m2w;
        const float* m2b = l ? cm2b + (l - 1) * 64       : c0m2b;
        const float* m4w = l ? cm4w + (l - 1) * 64 * 128 : c0m4w;
        const float* m4b = l ? cm4b + (l - 1) * 64       : c0m4b;
        const float* pbg = l ? bn_g + 64 * (l - 1) : nullptr;  // prev-layer bn
        const float* pbb = l ? bn_b + 64 * (l - 1) : nullptr;
        // extractor to flush: layer 0 -> adjacency (np), else fe of layer l-1
        const float* sta = l ? nullptr : (ST + ST_ATR);
        const float* ew1 = l ? fe1w + (l - 1) * 64 * 64 : np1_w;
        const float* eb1 = l ? fe1b + (l - 1) * 64      : np1_b;
        const float* ew2 = l ? fe2w + (l - 1) * 64 * 64 : np2_w;
        const float* ew3 = l ? fe3w + (l - 1) * 64 * 64 : np3_w;
        const int    eC  = l ? 64 : TWOF;

        int ldab = Cin + 8;
        size_t shAB = (size_t)(2 * 64 * ldab + 32 * 136) * 2 + 2 * 64 * 4;
        if (shAB < 64 * 136 * 2 + 256) shAB = 64 * 136 * 2 + 256;  // staging floor
        k_mixAB<<<2048, 256, shAB>>>(cur, Cin, m1w, m1b, m2w, m2b, ST, fold,
                                     pbg, pbb, sta, ew1, eb1, ew2, ew3, eC, AC,
                                     O1, O2);

        k_mma<<<dim3(4, 4, 64), 256, 2 * STG * 2>>>(O1, O2, M, ST, pbg, pbb, fold);

        bf16* nxt = (l == 0) ? V0 : ((l == 1) ? V1 : nullptr);
        int ld4 = 64 + Cin + 8;
        size_t sh4 = (size_t)(64 * ld4 + 32 * 136) * 2 + (64 + 192) * 4;
        k_mix4<<<2048, 256, sh4>>>(M, cur, Cin, m4w, m4b, fold, nxt, ST);

        cur = nxt;
    }

    k_head<<<1, 64>>>(ST, bn_g + 128, bn_b + 128,
                      fe1w + 2 * 64 * 64, fe1b + 2 * 64,
                      fe2w + 2 * 64 * 64, fe3w + 2 * 64 * 64,
                      AC, ac_w, ac_b, fl_w, fl_b, (float*)d_out);
}

// round 13
// speedup vs baseline: 1.6510x; 1.3197x over previous
#include <cuda_runtime.h>
#include <cuda_bf16.h>
#include <math.h>
#include <stdint.h>

#define NN   512
#define NP   (NN*NN)        // 262144
#define FIN  16
#define TWOF 32
#define EE   16384
#define NL   3

// g_ST layout
#define ST_SUM   0
#define ST_SQ    64
#define ST_TR    128
#define ST_S     192
#define ST_T     256
#define ST_ATR   320

typedef __nv_bfloat16 bf16;
typedef __nv_bfloat162 bf162;

// ---------------- scratch (device globals; no allocation allowed) ----------
__device__ bf16  g_Ub[32u*NP];        // bf16 adjacency (scatter target)
__device__ bf16  g_V0[64u*NP];
__device__ bf16  g_V1[64u*NP];
__device__ bf16  g_O1[64u*NP];
__device__ bf16  g_O2[64u*NP];
__device__ bf16  g_M [64u*NP];
__device__ float g_ST[448];
__device__ float g_AC[64];

#define MMA_BF16(d, a, b)                                                      \
    asm volatile(                                                              \
        "mma.sync.aligned.m16n8k16.row.col.f32.bf16.bf16.f32 "                 \
        "{%0,%1,%2,%3},{%4,%5,%6,%7},{%8,%9},{%0,%1,%2,%3};"                   \
        : "+f"(d[0]), "+f"(d[1]), "+f"(d[2]), "+f"(d[3])                       \
        : "r"(a[0]), "r"(a[1]), "r"(a[2]), "r"(a[3]), "r"(b[0]), "r"(b[1]))

#define LDSM4(R, addr)                                                         \
    asm volatile("ldmatrix.sync.aligned.m8n8.x4.shared.b16 {%0,%1,%2,%3},[%4];"\
        : "=r"(R[0]), "=r"(R[1]), "=r"(R[2]), "=r"(R[3]) : "r"(addr))

#define LDSM4T(R, addr)                                                        \
    asm volatile("ldmatrix.sync.aligned.m8n8.x4.trans.shared.b16 {%0,%1,%2,%3},[%4];"\
        : "=r"(R[0]), "=r"(R[1]), "=r"(R[2]), "=r"(R[3]) : "r"(addr))

__device__ __forceinline__ uint32_t smaddr(const void* p) {
    return (uint32_t)__cvta_generic_to_shared(p);
}
__device__ __forceinline__ void cp16(void* smem, const void* g) {
    asm volatile("cp.async.cg.shared.global [%0], [%1], 16;"
                 :: "r"(smaddr(smem)), "l"(g));
}
#define CP_COMMIT()  asm volatile("cp.async.commit_group;")
#define CP_WAIT(n)   asm volatile("cp.async.wait_group %0;" :: "n"(n))

// ---------------- init: zero bf16 adjacency + AC + ST ------------------------
__global__ void k_zero(uint4* Ub16, float* AC, float* ST) {
    int i = blockIdx.x * 256 + threadIdx.x;           // 4*NP uint4 words
    Ub16[i] = make_uint4(0u, 0u, 0u, 0u);
    if (i < 64)  AC[i] = 0.f;
    if (i < 448) ST[i] = 0.f;
}

// ---------------- scatter edges into A[c][src][dst] (bf16 atomics) -----------
__global__ void k_scatter(const float* __restrict__ x, const int* __restrict__ ei,
                          bf16* __restrict__ A) {
    int t = blockIdx.x * 256 + threadIdx.x;           // EE*32 threads
    int e = t >> 5, c = t & 31;
    int s = ei[e], d = ei[EE + e];
    float v = (c < FIN) ? x[s * FIN + c] : x[d * FIN + (c - FIN)];
    atomicAdd(&A[(size_t)c * NP + s * NN + d], __float2bfloat16_rn(v));
}

// ---------------- per-channel trace + total of A (bf16 in, fp32 reduce) ------
__global__ void k_ext_stats(const bf16* __restrict__ U, float* __restrict__ st) {
    int c = blockIdx.x;
    const bf16* u = U + (size_t)c * NP;
    const uint4* u8 = (const uint4*)u;                // 8 bf16 per uint4
    float tot = 0.f, tr = 0.f;
    for (int i = threadIdx.x; i < NP / 8; i += 256) {
        uint4 v = u8[i];
        float2 f0 = __bfloat1622float2(*(bf162*)&v.x);
        float2 f1 = __bfloat1622float2(*(bf162*)&v.y);
        float2 f2 = __bfloat1622float2(*(bf162*)&v.z);
        float2 f3 = __bfloat1622float2(*(bf162*)&v.w);
        tot += (f0.x + f0.y) + (f1.x + f1.y) + (f2.x + f2.y) + (f3.x + f3.y);
    }
    for (int i = threadIdx.x; i < NN; i += 256) tr += __bfloat162float(u[i * (NN + 1)]);
    __shared__ float s1[256], s2[256];
    s1[threadIdx.x] = tot; s2[threadIdx.x] = tr; __syncthreads();
    for (int o = 128; o > 0; o >>= 1) {
        if (threadIdx.x < o) { s1[threadIdx.x] += s1[threadIdx.x+o]; s2[threadIdx.x] += s2[threadIdx.x+o]; }
        __syncthreads();
    }
    if (threadIdx.x == 0) { st[c] = s2[0]; st[64 + c] = s1[0]; }
}

// ---------------- fused mix1+mix2 (+ BN fold + prev-layer extractor flush) ---
// 2 position-tiles per block; double-buffered U staging.
__global__ __launch_bounds__(256) void k_mixAB(
    const bf16* __restrict__ in, int Ct,
    const float* __restrict__ W1, const float* __restrict__ b1,
    const float* __restrict__ W2, const float* __restrict__ b2,
    const float* __restrict__ ST, int fold,
    const float* __restrict__ bng, const float* __restrict__ bnb,
    const float* __restrict__ STA,       // adjacency stats (layer 0) or null
    const float* __restrict__ ew1, const float* __restrict__ eb1,
    const float* __restrict__ ew2, const float* __restrict__ ew3, int eC,
    float* __restrict__ AC,
    bf16* __restrict__ O1, bf16* __restrict__ O2) {
    const int ld2 = Ct + 8;                 // row stride: (Ct+8)*2B = 16*odd
    extern __shared__ char shraw[];
    bf16*  Ws1 = (bf16*)shraw;              // [64][ld2]
    bf16*  Ws2 = Ws1 + 64 * ld2;
    float* bs1 = (float*)(Ws2 + 64 * ld2);
    float* bs2 = bs1 + 64;
    bf16*  Us  = (bf16*)(bs2 + 64);         // 2 x [32][136]
    __shared__ float sS[64], sT[64], osh[64];

    // per-block BN params from raw stats (finalize folded in)
    if (fold && threadIdx.x < 64) {
        int c = threadIdx.x;
        float sum = ST[ST_SUM + c], sq = ST[ST_SQ + c];
        float m   = sum / (float)NP;
        float var = sq / (float)NP - m * m;
        float s   = bng[c] * rsqrtf(var + 1e-5f);
        sS[c] = s; sT[c] = bnb[c] - m * s;
    }
    __syncthreads();

    // block 0: flush previous stage's extractor into AC
    if (blockIdx.x == 0 && threadIdx.x < 64) {
        int h = threadIdx.x;
        float o = eb1[h];
        for (int c = 0; c < eC; c++) {
            float str, stot;
            if (STA) { str = STA[c]; stot = STA[64 + c]; }
            else {
                float s = sS[c], t = sT[c];
                str  = ST[ST_TR  + c] * s + 512.f * t;
                stot = ST[ST_SUM + c] * s + (float)NP * t;
            }
            o += ew1[h * eC + c] * (str / 512.f)
               + ew2[h * eC + c] * ((stot - str) / (512.f * 511.f));
        }
        osh[h] = o;
    }
    __syncthreads();
    if (blockIdx.x == 0 && threadIdx.x < 64) {
        int h = threadIdx.x;
        float a = osh[h];
        for (int k = 0; k < 64; k++) a += ew3[h * 64 + k] * fmaxf(osh[k], 0.f);
        AC[h] += a;
    }

    for (int i = threadIdx.x; i < 64 * Ct; i += 256) {
        int o = i / Ct, c = i - o * Ct;
        float s = fold ? sS[c] : 1.f;
        Ws1[o * ld2 + c] = __float2bfloat16_rn(W1[i] * s);
        Ws2[o * ld2 + c] = __float2bfloat16_rn(W2[i] * s);
    }
    if (threadIdx.x < 64) {
        int o = threadIdx.x;
        float a1 = b1[o], a2 = b2[o];
        if (fold)
            for (int c = 0; c < Ct; c++) {
                float t = sT[c];
                a1 += W1[o * Ct + c] * t;
                a2 += W2[o * Ct + c] * t;
            }
        bs1[o] = a1; bs2[o] = a2;
    }
    __syncthreads();

    const int lane = threadIdx.x & 31;
    const int wid  = threadIdx.x >> 5;
    const int cg = wid & 3, rg = wid >> 2;
    const int lq = lane & 3, lr = lane >> 2;
    const int lml = lane & 15, lmh = (lane >> 4) << 3;
    const int nch = Ct >> 5;                // 1 or 2

    float bb1[2][2], bb2[2][2];
#pragma unroll
    for (int mi = 0; mi < 2; mi++) {
        int o0 = rg * 32 + mi * 16 + lr;
        bb1[mi][0] = bs1[o0]; bb1[mi][1] = bs1[o0 + 8];
        bb2[mi][0] = bs2[o0]; bb2[mi][1] = bs2[o0 + 8];
    }

    for (int t = 0; t < 2; t++) {
        const int p0 = blockIdx.x * 256 + t * 128;

        float acc1[2][4][4], acc2[2][4][4];
#pragma unroll
        for (int mi = 0; mi < 2; mi++)
#pragma unroll
            for (int nj = 0; nj < 4; nj++)
#pragma unroll
                for (int q = 0; q < 4; q++) { acc1[mi][nj][q] = 0.f; acc2[mi][nj][q] = 0.f; }

        // stage all k-chunks (<=2) up front
        for (int c = 0; c < nch; c++) {
            bf16* Ub = Us + c * (32 * 136);
            for (int i = threadIdx.x; i < 512; i += 256) {
                int kk = i >> 4, c8 = (i & 15) << 3;
                cp16(Ub + kk * 136 + c8, in + (size_t)(c * 32 + kk) * NP + p0 + c8);
            }
            CP_COMMIT();
        }

        auto computeChunk = [&](const bf16* Ub, int k0g) {
#pragma unroll
            for (int kk = 0; kk < 32; kk += 16) {
                uint32_t a1[2][4], a2[2][4], bq[2][4];
#pragma unroll
                for (int mi = 0; mi < 2; mi++) {
                    int r = rg * 32 + mi * 16 + lml;
                    LDSM4(a1[mi], smaddr(Ws1 + r * ld2 + k0g + kk + lmh));
                    LDSM4(a2[mi], smaddr(Ws2 + r * ld2 + k0g + kk + lmh));
                }
#pragma unroll
                for (int njp = 0; njp < 2; njp++)
                    LDSM4T(bq[njp], smaddr(Ub + (kk + lml) * 136 + cg * 32 + njp * 16 + lmh));
#pragma unroll
                for (int mi = 0; mi < 2; mi++)
#pragma unroll
                    for (int njp = 0; njp < 2; njp++) {
                        MMA_BF16(acc1[mi][2*njp],   a1[mi], (bq[njp]));
                        MMA_BF16(acc1[mi][2*njp+1], a1[mi], (bq[njp]+2));
                        MMA_BF16(acc2[mi][2*njp],   a2[mi], (bq[njp]));
                        MMA_BF16(acc2[mi][2*njp+1], a2[mi], (bq[njp]+2));
                    }
            }
        };

        if (nch == 2) {
            CP_WAIT(1); __syncthreads();
            computeChunk(Us, 0);
            CP_WAIT(0); __syncthreads();
            computeChunk(Us + 32 * 136, 32);
        } else {
            CP_WAIT(0); __syncthreads();
            computeChunk(Us, 0);
        }

        // epilogue: stage in Us area (weights preserved)
        bf16* Os = Us;                              // [64][136]
        __syncthreads();
#pragma unroll
        for (int mi = 0; mi < 2; mi++) {
            int o0 = rg * 32 + mi * 16 + lr, o1 = o0 + 8;
#pragma unroll
            for (int nj = 0; nj < 4; nj++) {
                int col = cg * 32 + nj * 8 + 2 * lq;
                *(bf162*)(Os + o0 * 136 + col) =
                    __floats2bfloat162_rn(acc1[mi][nj][0] + bb1[mi][0], acc1[mi][nj][1] + bb1[mi][0]);
                *(bf162*)(Os + o1 * 136 + col) =
                    __floats2bfloat162_rn(acc1[mi][nj][2] + bb1[mi][1], acc1[mi][nj][3] + bb1[mi][1]);
            }
        }
        __syncthreads();
        for (int i = threadIdx.x * 8; i < 64 * 128; i += 2048) {
            int o = i >> 7, c = i & 127;
            *(float4*)(O1 + (size_t)o * NP + p0 + c) = *(float4*)(Os + o * 136 + c);
        }
        __syncthreads();
#pragma unroll
        for (int mi = 0; mi < 2; mi++) {
            int o0 = rg * 32 + mi * 16 + lr, o1 = o0 + 8;
#pragma unroll
            for (int nj = 0; nj < 4; nj++) {
                int col = cg * 32 + nj * 8 + 2 * lq;
                *(bf162*)(Os + o0 * 136 + col) =
                    __floats2bfloat162_rn(acc2[mi][nj][0] + bb2[mi][0], acc2[mi][nj][1] + bb2[mi][0]);
                *(bf162*)(Os + o1 * 136 + col) =
                    __floats2bfloat162_rn(acc2[mi][nj][2] + bb2[mi][1], acc2[mi][nj][3] + bb2[mi][1]);
            }
        }
        __syncthreads();
        for (int i = threadIdx.x * 8; i < 64 * 128; i += 2048) {
            int o = i >> 7, c = i & 127;
            *(float4*)(O2 + (size_t)o * NP + p0 + c) = *(float4*)(Os + o * 136 + c);
        }
        __syncthreads();        // Us reused for next tile's staging
    }
}

// ---------------- batched 512^3 bf16 GEMM, cp.async double-buffered ----------
#define LDA 72      // 144B row stride
#define LDB 136     // 272B row stride
#define STG (128*LDA + 64*LDB)   // bf16 elems per stage = 17920
__global__ __launch_bounds__(256) void k_mma(const bf16* __restrict__ A,
                                             const bf16* __restrict__ B,
                                             bf16* __restrict__ C,
                                             float* __restrict__ ST,
                                             const float* __restrict__ bng,
                                             const float* __restrict__ bnb,
                                             int fold) {
    extern __shared__ bf16 dsm[];                  // 2 stages
    const int ch = blockIdx.z;
    const bf16* Ab = A + (size_t)ch * NP;
    const bf16* Bb = B + (size_t)ch * NP;
    bf16*       Cb = C + (size_t)ch * NP;
    const int tid  = threadIdx.x;
    const int lane = tid & 31, wid = tid >> 5;
    const int wr = wid >> 1, wc = wid & 1;
    const int lq = lane & 3, lr = lane >> 2;
    const int lml = lane & 15, lmh = (lane >> 4) << 3;
    const int rowBase = blockIdx.y * 128;
    const int colBase = blockIdx.x * 128;

    float acc[2][8][4];
#pragma unroll
    for (int mi = 0; mi < 2; mi++)
#pragma unroll
        for (int nj = 0; nj < 8; nj++)
#pragma unroll
            for (int q = 0; q < 4; q++) acc[mi][nj][q] = 0.f;

    auto loadTile = [&](int t, int s) {
        bf16* As = dsm + s * STG;
        bf16* Bs = As + 128 * LDA;
        int k0 = t * 64;
#pragma unroll
        for (int i = 0; i < 4; i++) {              // A: 128 rows x 64 bf16
            int lin = tid + i * 256;
            int r = lin >> 3, kc = (lin & 7) << 3;
            cp16(As + r * LDA + kc, Ab + (size_t)(rowBase + r) * NN + k0 + kc);
        }
#pragma unroll
        for (int i = 0; i < 4; i++) {              // B: 64 rows x 128 bf16
            int lin = tid + i * 256;
            int kk = lin >> 4, c8 = (lin & 15) << 3;
            cp16(Bs + kk * LDB + c8, Bb + (size_t)(k0 + kk) * NN + colBase + c8);
        }
        CP_COMMIT();
    };

    loadTile(0, 0);

    // block (0,0,0): snapshot s,t for mix4, then reset raw accumulators
    if (blockIdx.x == 0 && blockIdx.y == 0 && blockIdx.z == 0) {
        if (fold && tid < 64) {
            int c = tid;
            float sum = ST[ST_SUM + c], sq = ST[ST_SQ + c];
            float m   = sum / (float)NP;
            float var = sq / (float)NP - m * m;
            float s   = bng[c] * rsqrtf(var + 1e-5f);
            ST[ST_S + c] = s; ST[ST_T + c] = bnb[c] - m * s;
        }
    }
    __syncthreads();
    if (blockIdx.x == 0 && blockIdx.y == 0 && blockIdx.z == 0 && tid < 192)
        ST[ST_SUM + tid] = 0.f;

    for (int t = 0; t < 8; t++) {                  // k-tiles of 64
        if (t < 7) {
            loadTile(t + 1, (t + 1) & 1);
            CP_WAIT(1);
        } else {
            CP_WAIT(0);
        }
        __syncthreads();
        const bf16* As = dsm + (t & 1) * STG;
        const bf16* Bs = As + 128 * LDA;
#pragma unroll
        for (int kk = 0; kk < 64; kk += 16) {
            uint32_t a[2][4], bq[4][4];
#pragma unroll
            for (int mi = 0; mi < 2; mi++) {
                int r = wr * 32 + mi * 16 + lml;
                LDSM4(a[mi], smaddr(As + r * LDA + kk + lmh));
            }
#pragma unroll
            for (int njp = 0; njp < 4; njp++)
                LDSM4T(bq[njp], smaddr(Bs + (kk + lml) * LDB + wc * 64 + njp * 16 + lmh));
#pragma unroll
            for (int mi = 0; mi < 2; mi++)
#pragma unroll
                for (int njp = 0; njp < 4; njp++) {
                    MMA_BF16(acc[mi][2*njp],   a[mi], (bq[njp]));
                    MMA_BF16(acc[mi][2*njp+1], a[mi], (bq[njp]+2));
                }
        }
        __syncthreads();
    }

    // coalesced epilogue: stage 128x128 tile in smem (row stride 136)
    bf16* Cs = dsm;
#pragma unroll
    for (int mi = 0; mi < 2; mi++) {
        int r0 = wr * 32 + mi * 16 + lr;
#pragma unroll
        for (int nj = 0; nj < 8; nj++) {
            int col = wc * 64 + nj * 8 + 2 * lq;
            *(bf162*)(Cs + r0 * 136 + col) =
                __floats2bfloat162_rn(acc[mi][nj][0], acc[mi][nj][1]);
            *(bf162*)(Cs + (r0 + 8) * 136 + col) =
                __floats2bfloat162_rn(acc[mi][nj][2], acc[mi][nj][3]);
        }
    }
    __syncthreads();
    for (int i = tid * 8; i < 128 * 128; i += 2048) {
        int r = i >> 7, c = i & 127;
        *(float4*)(Cb + (size_t)(rowBase + r) * NN + colBase + c) =
            *(float4*)(Cs + r * 136 + c);
    }
}

// ---------------- mix4: concat(M, cur) -> out (bf16), stats epilogue ---------
// 2 position-tiles per block; 4-buffer cp.async staging (all chunks in flight).
__global__ __launch_bounds__(256) void k_mix4(
    const bf16* __restrict__ Mt, const bf16* __restrict__ cur, int C2,
    const float* __restrict__ W, const float* __restrict__ bias,
    int fold, bf16* __restrict__ out, float* __restrict__ ST) {
    const int Ct = 64 + C2;
    const int ld2 = Ct + 8;
    extern __shared__ char shraw[];
    bf16*  Ws = (bf16*)shraw;               // [64][ld2]
    float* bs = (float*)(Ws + 64 * ld2);    // 64
    bf16*  Us = (bf16*)(bs + 64);           // 4 x [32][136]
    float* sSum = (float*)(Us + 4 * 32 * 136);  // 64
    float* sSq  = sSum + 64;                // 64
    float* sTr  = sSq + 64;                 // 64

    for (int i = threadIdx.x; i < 64 * Ct; i += 256) {
        int o = i / Ct, c = i - o * Ct;
        float s = (c >= 64 && fold) ? ST[ST_S + c - 64] : 1.f;
        Ws[o * ld2 + c] = __float2bfloat16_rn(W[i] * s);
    }
    if (threadIdx.x < 64) {
        int o = threadIdx.x;
        float a = bias[o];
        if (fold)
            for (int c = 64; c < Ct; c++) a += W[o * Ct + c] * ST[ST_T + c - 64];
        bs[o] = a;
    }
    if (threadIdx.x < 192) sSum[threadIdx.x] = 0.f;   // zeros sum/sq/tr
    __syncthreads();

    const int lane = threadIdx.x & 31;
    const int wid  = threadIdx.x >> 5;
    const int cg = wid & 3, rg = wid >> 2;
    const int lq = lane & 3, lr = lane >> 2;
    const int lml = lane & 15, lmh = (lane >> 4) << 3;
    const int nch = Ct >> 5;                // 3 or 4

    float bb[2][2];
#pragma unroll
    for (int mi = 0; mi < 2; mi++) {
        int o0 = rg * 32 + mi * 16 + lr;
        bb[mi][0] = bs[o0]; bb[mi][1] = bs[o0 + 8];
    }

    for (int t = 0; t < 2; t++) {
        const int p0 = blockIdx.x * 256 + t * 128;

        float acc[2][4][4];
#pragma unroll
        for (int mi = 0; mi < 2; mi++)
#pragma unroll
            for (int nj = 0; nj < 4; nj++)
#pragma unroll
                for (int q = 0; q < 4; q++) acc[mi][nj][q] = 0.f;

        // stage all k-chunks (3 or 4) up front
        for (int c = 0; c < nch; c++) {
            bf16* Ub = Us + c * (32 * 136);
            int cb = c * 32;
            for (int i = threadIdx.x; i < 512; i += 256) {
                int kk = i >> 4, c8 = (i & 15) << 3;
                int ch = cb + kk;
                const bf16* src = (ch < 64) ? Mt + (size_t)ch * NP
                                            : cur + (size_t)(ch - 64) * NP;
                cp16(Ub + kk * 136 + c8, src + p0 + c8);
            }
            CP_COMMIT();
        }

        auto computeChunk = [&](const bf16* Ub, int k0g) {
#pragma unroll
            for (int kk = 0; kk < 32; kk += 16) {
                uint32_t a[2][4], bq[2][4];
#pragma unroll
                for (int mi = 0; mi < 2; mi++) {
                    int r = rg * 32 + mi * 16 + lml;
                    LDSM4(a[mi], smaddr(Ws + r * ld2 + k0g + kk + lmh));
                }
#pragma unroll
                for (int njp = 0; njp < 2; njp++)
                    LDSM4T(bq[njp], smaddr(Ub + (kk + lml) * 136 + cg * 32 + njp * 16 + lmh));
#pragma unroll
                for (int mi = 0; mi < 2; mi++)
#pragma unroll
                    for (int njp = 0; njp < 2; njp++) {
                        MMA_BF16(acc[mi][2*njp],   a[mi], (bq[njp]));
                        MMA_BF16(acc[mi][2*njp+1], a[mi], (bq[njp]+2));
                    }
            }
        };

        if (nch == 4) {
            CP_WAIT(3); __syncthreads(); computeChunk(Us,             0);
            CP_WAIT(2); __syncthreads(); computeChunk(Us + 32*136,   32);
            CP_WAIT(1); __syncthreads(); computeChunk(Us + 2*32*136, 64);
            CP_WAIT(0); __syncthreads(); computeChunk(Us + 3*32*136, 96);
        } else {
            CP_WAIT(2); __syncthreads(); computeChunk(Us,             0);
            CP_WAIT(1); __syncthreads(); computeChunk(Us + 32*136,   32);
            CP_WAIT(0); __syncthreads(); computeChunk(Us + 2*32*136, 64);
        }

        int dp = ((p0 + 512) / 513) * 513;          // diagonal column inside tile
        bool hasDiag = (dp < p0 + 128);
        bf16* Os = Us;                              // [64][136] staging in U area
        __syncthreads();

#pragma unroll
        for (int mi = 0; mi < 2; mi++) {
            int o0 = rg * 32 + mi * 16 + lr, o1 = o0 + 8;
            float b0 = bb[mi][0], b1v = bb[mi][1];
            float s0 = 0.f, q0 = 0.f, s1 = 0.f, q1 = 0.f;
#pragma unroll
            for (int nj = 0; nj < 4; nj++) {
                int col = cg * 32 + nj * 8 + 2 * lq;
                float v00 = acc[mi][nj][0] + b0, v01 = acc[mi][nj][1] + b0;
                float v10 = acc[mi][nj][2] + b1v, v11 = acc[mi][nj][3] + b1v;
                if (out) {
                    *(bf162*)(Os + o0 * 136 + col) = __floats2bfloat162_rn(v00, v01);
                    *(bf162*)(Os + o1 * 136 + col) = __floats2bfloat162_rn(v10, v11);
                }
                s0 += v00 + v01; q0 += v00 * v00 + v01 * v01;
                s1 += v10 + v11; q1 += v10 * v10 + v11 * v11;
                if (hasDiag) {
                    int gcol = p0 + col;
                    if (gcol == dp)     { atomicAdd(&sTr[o0], v00); atomicAdd(&sTr[o1], v10); }
                    if (gcol + 1 == dp) { atomicAdd(&sTr[o0], v01); atomicAdd(&sTr[o1], v11); }
                }
            }
#pragma unroll
            for (int off = 1; off < 4; off <<= 1) {
                s0 += __shfl_xor_sync(0xffffffffu, s0, off);
                q0 += __shfl_xor_sync(0xffffffffu, q0, off);
                s1 += __shfl_xor_sync(0xffffffffu, s1, off);
                q1 += __shfl_xor_sync(0xffffffffu, q1, off);
            }
            if (lq == 0) {
                atomicAdd(&sSum[o0], s0); atomicAdd(&sSq[o0], q0);
                atomicAdd(&sSum[o1], s1); atomicAdd(&sSq[o1], q1);
            }
        }
        __syncthreads();
        if (out) {
            for (int i = threadIdx.x * 8; i < 64 * 128; i += 2048) {
                int o = i >> 7, c = i & 127;
                *(float4*)(out + (size_t)o * NP + p0 + c) = *(float4*)(Os + o * 136 + c);
            }
            __syncthreads();        // Us reused for next tile's staging
        }
    }

    if (threadIdx.x < 64) {
        int c = threadIdx.x;
        atomicAdd(&ST[ST_SUM + c], sSum[c]);
        atomicAdd(&ST[ST_SQ  + c], sSq[c]);
        if (sTr[c] != 0.f) atomicAdd(&ST[ST_TR + c], sTr[c]);
    }
}

// ---------------- head: layer-2 finalize + extractor + classifier ------------
__global__ void k_head(float* __restrict__ ST,
                       const float* __restrict__ g, const float* __restrict__ b,
                       const float* __restrict__ ew1, const float* __restrict__ eb1,
                       const float* __restrict__ ew2, const float* __restrict__ ew3,
                       const float* __restrict__ acc,
                       const float* __restrict__ ac_w, const float* __restrict__ ac_b,
                       const float* __restrict__ fl_w, const float* __restrict__ fl_b,
                       float* __restrict__ out) {
    __shared__ float o[64], t[64], osh[64], lg[10];
    int h = threadIdx.x;                               // 64 threads
    {
        float sum = ST[ST_SUM + h], sq = ST[ST_SQ + h], tr = ST[ST_TR + h];
        float m   = sum / (float)NP;
        float var = sq / (float)NP - m * m;
        float s   = g[h] * rsqrtf(var + 1e-5f);
        float tt  = b[h] - m * s;
        o[h] = tr * s + 512.f * tt;                    // str
        t[h] = sum * s + (float)NP * tt;               // stot
    }
    __syncthreads();
    float oo = eb1[h];
    for (int c = 0; c < 64; c++)
        oo += ew1[h * 64 + c] * (o[c] / 512.f)
            + ew2[h * 64 + c] * ((t[c] - o[c]) / (512.f * 511.f));
    osh[h] = oo;
    __syncthreads();
    float a = osh[h];
    for (int k = 0; k < 64; k++) a += ew3[h * 64 + k] * fmaxf(osh[k], 0.f);
    float accv = acc[h] + a;
    __syncthreads();
    o[h] = fmaxf(accv, 0.f) / (float)NL;
    __syncthreads();
    float s2 = ac_b[h];
    for (int k = 0; k < 64; k++) s2 += ac_w[h * 64 + k] * o[k];
    t[h] = o[h] + fmaxf(s2, 0.f);
    __syncthreads();
    if (h < 10) {
        float l = fl_b[h];
        for (int k = 0; k < 64; k++) l += fl_w[h * 64 + k] * t[k];
        lg[h] = l;
    }
    __syncthreads();
    if (h < 10) {
        float m = -1e30f;
        for (int i = 0; i < 10; i++) m = fmaxf(m, lg[i]);
        float se = 0.f;
        for (int i = 0; i < 10; i++) se += expf(lg[i] - m);
        out[h] = lg[h] - m - logf(se);
    }
}

// ---------------- launch -----------------------------------------------------
extern "C" void kernel_launch(void* const* d_in, const int* in_sizes, int n_in,
                              void* d_out, int out_size) {
    const float* x     = (const float*)d_in[0];
    const int*   ei    = (const int*)  d_in[1];
    const float* np1_w = (const float*)d_in[2];
    const float* np1_b = (const float*)d_in[3];
    const float* np2_w = (const float*)d_in[4];
    const float* np3_w = (const float*)d_in[5];
    const float* c0m1w = (const float*)d_in[6];
    const float* c0m1b = (const float*)d_in[7];
    const float* c0m2w = (const float*)d_in[8];
    const float* c0m2b = (const float*)d_in[9];
    const float* c0m4w = (const float*)d_in[10];
    const float* c0m4b = (const float*)d_in[11];
    const float* cm1w  = (const float*)d_in[12];
    const float* cm1b  = (const float*)d_in[13];
    const float* cm2w  = (const float*)d_in[14];
    const float* cm2b  = (const float*)d_in[15];
    const float* cm4w  = (const float*)d_in[16];
    const float* cm4b  = (const float*)d_in[17];
    const float* bn_g  = (const float*)d_in[18];
    const float* bn_b  = (const float*)d_in[19];
    const float* fe1w  = (const float*)d_in[20];
    const float* fe1b  = (const float*)d_in[21];
    const float* fe2w  = (const float*)d_in[22];
    const float* fe3w  = (const float*)d_in[23];
    const float* ac_w  = (const float*)d_in[24];
    const float* ac_b  = (const float*)d_in[25];
    const float* fl_w  = (const float*)d_in[26];
    const float* fl_b  = (const float*)d_in[27];

    float *ST, *AC;
    bf16 *Ub, *V0, *V1, *O1, *O2, *M;
    cudaGetSymbolAddress((void**)&Ub, g_Ub);
    cudaGetSymbolAddress((void**)&V0, g_V0);
    cudaGetSymbolAddress((void**)&V1, g_V1);
    cudaGetSymbolAddress((void**)&O1, g_O1);
    cudaGetSymbolAddress((void**)&O2, g_O2);
    cudaGetSymbolAddress((void**)&M,  g_M);
    cudaGetSymbolAddress((void**)&ST, g_ST);
    cudaGetSymbolAddress((void**)&AC, g_AC);

    static bool attr_done = false;
    if (!attr_done) {
        cudaFuncSetAttribute(k_mma,   cudaFuncAttributeMaxDynamicSharedMemorySize, 2 * STG * 2);
        cudaFuncSetAttribute(k_mixAB, cudaFuncAttributeMaxDynamicSharedMemorySize, 64 * 1024);
        cudaFuncSetAttribute(k_mix4,  cudaFuncAttributeMaxDynamicSharedMemorySize, 64 * 1024);
        attr_done = true;
    }

    k_zero<<<(4u * NP) / 256, 256>>>((uint4*)Ub, AC, ST);
    k_scatter<<<(EE * 32) / 256, 256>>>(x, ei, Ub);
    k_ext_stats<<<TWOF, 256>>>(Ub, ST + ST_ATR);

    const bf16* cur = Ub;
    for (int l = 0; l < NL; l++) {
        const int Cin = l ? 64 : TWOF;
        const int fold = (l > 0) ? 1 : 0;
        const float* m1w = l ? cm1w + (l - 1) * 64 * 64  : c0m1w;
        const float* m1b = l ? cm1b + (l - 1) * 64       : c0m1b;
        const float* m2w = l ? cm2w + (l - 1) * 64 * 64  : c0m2w;
        const float* m2b = l ? cm2b + (l - 1) * 64       : c0m2b;
        const float* m4w = l ? cm4w + (l - 1) * 64 * 128 : c0m4w;
        const float* m4b = l ? cm4b + (l - 1) * 64       : c0m4b;
        const float* pbg = l ? bn_g + 64 * (l - 1) : nullptr;  // prev-layer bn
        const float* pbb = l ? bn_b + 64 * (l - 1) : nullptr;
        // extractor to flush: layer 0 -> adjacency (np), else fe of layer l-1
        const float* sta = l ? nullptr : (ST + ST_ATR);
        const float* ew1 = l ? fe1w + (l - 1) * 64 * 64 : np1_w;
        const float* eb1 = l ? fe1b + (l - 1) * 64      : np1_b;
        const float* ew2 = l ? fe2w + (l - 1) * 64 * 64 : np2_w;
        const float* ew3 = l ? fe3w + (l - 1) * 64 * 64 : np3_w;
        const int    eC  = l ? 64 : TWOF;

        size_t shAB = (size_t)(2 * 64 * (Cin + 8) + 2 * 32 * 136) * 2 + 2 * 64 * 4;
        k_mixAB<<<1024, 256, shAB>>>(cur, Cin, m1w, m1b, m2w, m2b, ST, fold,
                                     pbg, pbb, sta, ew1, eb1, ew2, ew3, eC, AC,
                                     O1, O2);

        k_mma<<<dim3(4, 4, 64), 256, 2 * STG * 2>>>(O1, O2, M, ST, pbg, pbb, fold);

        bf16* nxt = (l == 0) ? V0 : ((l == 1) ? V1 : nullptr);
        size_t sh4 = (size_t)(64 * (64 + Cin + 8) + 4 * 32 * 136) * 2 + (64 + 192) * 4;
        k_mix4<<<1024, 256, sh4>>>(M, cur, Cin, m4w, m4b, fold, nxt, ST);

        cur = nxt;
    }

    k_head<<<1, 64>>>(ST, bn_g + 128, bn_b + 128,
                      fe1w + 2 * 64 * 64, fe1b + 2 * 64,
                      fe2w + 2 * 64 * 64, fe3w + 2 * 64 * 64,
                      AC, ac_w, ac_b, fl_w, fl_b, (float*)d_out);
}

// round 14
// speedup vs baseline: 1.6832x; 1.0195x over previous
#include <cuda_runtime.h>
#include <cuda_bf16.h>
#include <math.h>
#include <stdint.h>

#define NN   512
#define NP   (NN*NN)        // 262144
#define FIN  16
#define TWOF 32
#define EE   16384
#define NL   3

// g_ST layout
#define ST_SUM   0
#define ST_SQ    64
#define ST_TR    128
#define ST_S     192
#define ST_T     256
#define ST_ATR   320

typedef __nv_bfloat16 bf16;
typedef __nv_bfloat162 bf162;

// ---------------- scratch (device globals; no allocation allowed) ----------
__device__ bf16  g_Ub[32u*NP];        // bf16 adjacency (scatter target)
__device__ bf16  g_V0[64u*NP];
__device__ bf16  g_V1[64u*NP];
__device__ bf16  g_O1[64u*NP];
__device__ bf16  g_O2[64u*NP];
__device__ bf16  g_M [64u*NP];
__device__ float g_ST[448];
__device__ float g_AC[64];

#define MMA_BF16(d, a, b)                                                      \
    asm volatile(                                                              \
        "mma.sync.aligned.m16n8k16.row.col.f32.bf16.bf16.f32 "                 \
        "{%0,%1,%2,%3},{%4,%5,%6,%7},{%8,%9},{%0,%1,%2,%3};"                   \
        : "+f"(d[0]), "+f"(d[1]), "+f"(d[2]), "+f"(d[3])                       \
        : "r"(a[0]), "r"(a[1]), "r"(a[2]), "r"(a[3]), "r"(b[0]), "r"(b[1]))

#define LDSM4(R, addr)                                                         \
    asm volatile("ldmatrix.sync.aligned.m8n8.x4.shared.b16 {%0,%1,%2,%3},[%4];"\
        : "=r"(R[0]), "=r"(R[1]), "=r"(R[2]), "=r"(R[3]) : "r"(addr))

#define LDSM4T(R, addr)                                                        \
    asm volatile("ldmatrix.sync.aligned.m8n8.x4.trans.shared.b16 {%0,%1,%2,%3},[%4];"\
        : "=r"(R[0]), "=r"(R[1]), "=r"(R[2]), "=r"(R[3]) : "r"(addr))

__device__ __forceinline__ uint32_t smaddr(const void* p) {
    return (uint32_t)__cvta_generic_to_shared(p);
}
__device__ __forceinline__ void cp16(void* smem, const void* g) {
    asm volatile("cp.async.cg.shared.global [%0], [%1], 16;"
                 :: "r"(smaddr(smem)), "l"(g));
}
#define CP_COMMIT()  asm volatile("cp.async.commit_group;")
#define CP_WAIT(n)   asm volatile("cp.async.wait_group %0;" :: "n"(n))

// ---------------- init: zero bf16 adjacency + AC + ST ------------------------
__global__ void k_zero(uint4* Ub16, float* AC, float* ST) {
    int i = blockIdx.x * 256 + threadIdx.x;           // 4*NP uint4 words
    Ub16[i] = make_uint4(0u, 0u, 0u, 0u);
    if (i < 64)  AC[i] = 0.f;
    if (i < 448) ST[i] = 0.f;
}

// ---------------- scatter edges into A[c][src][dst] (bf16 atomics) -----------
__global__ void k_scatter(const float* __restrict__ x, const int* __restrict__ ei,
                          bf16* __restrict__ A) {
    int t = blockIdx.x * 256 + threadIdx.x;           // EE*32 threads
    int e = t >> 5, c = t & 31;
    int s = ei[e], d = ei[EE + e];
    float v = (c < FIN) ? x[s * FIN + c] : x[d * FIN + (c - FIN)];
    atomicAdd(&A[(size_t)c * NP + s * NN + d], __float2bfloat16_rn(v));
}

// ---------------- per-channel trace + total of A (bf16 in, fp32 reduce) ------
__global__ void k_ext_stats(const bf16* __restrict__ U, float* __restrict__ st) {
    int c = blockIdx.x;
    const bf16* u = U + (size_t)c * NP;
    const uint4* u8 = (const uint4*)u;                // 8 bf16 per uint4
    float tot = 0.f, tr = 0.f;
    for (int i = threadIdx.x; i < NP / 8; i += 256) {
        uint4 v = u8[i];
        float2 f0 = __bfloat1622float2(*(bf162*)&v.x);
        float2 f1 = __bfloat1622float2(*(bf162*)&v.y);
        float2 f2 = __bfloat1622float2(*(bf162*)&v.z);
        float2 f3 = __bfloat1622float2(*(bf162*)&v.w);
        tot += (f0.x + f0.y) + (f1.x + f1.y) + (f2.x + f2.y) + (f3.x + f3.y);
    }
    for (int i = threadIdx.x; i < NN; i += 256) tr += __bfloat162float(u[i * (NN + 1)]);
    __shared__ float s1[256], s2[256];
    s1[threadIdx.x] = tot; s2[threadIdx.x] = tr; __syncthreads();
    for (int o = 128; o > 0; o >>= 1) {
        if (threadIdx.x < o) { s1[threadIdx.x] += s1[threadIdx.x+o]; s2[threadIdx.x] += s2[threadIdx.x+o]; }
        __syncthreads();
    }
    if (threadIdx.x == 0) { st[c] = s2[0]; st[64 + c] = s1[0]; }
}

// ---------------- fused mix1+mix2 (+ BN fold + prev-layer extractor flush) ---
// 2 position-tiles per block; dual epilogue staging (O1+O2 in one sync phase).
__global__ __launch_bounds__(256) void k_mixAB(
    const bf16* __restrict__ in, int Ct,
    const float* __restrict__ W1, const float* __restrict__ b1,
    const float* __restrict__ W2, const float* __restrict__ b2,
    const float* __restrict__ ST, int fold,
    const float* __restrict__ bng, const float* __restrict__ bnb,
    const float* __restrict__ STA,       // adjacency stats (layer 0) or null
    const float* __restrict__ ew1, const float* __restrict__ eb1,
    const float* __restrict__ ew2, const float* __restrict__ ew3, int eC,
    float* __restrict__ AC,
    bf16* __restrict__ O1, bf16* __restrict__ O2) {
    const int ld2 = Ct + 8;                 // row stride: (Ct+8)*2B = 16*odd
    extern __shared__ char shraw[];
    bf16*  Ws1 = (bf16*)shraw;              // [64][ld2]
    bf16*  Ws2 = Ws1 + 64 * ld2;
    float* bs1 = (float*)(Ws2 + 64 * ld2);
    float* bs2 = bs1 + 64;
    bf16*  Us  = (bf16*)(bs2 + 64);         // 2 x [32][136]  (also O1 staging)
    bf16*  Os2 = Us + 2 * 32 * 136;         // [64][136] extra O2 staging
    __shared__ float sS[64], sT[64], osh[64];

    // per-block BN params from raw stats (finalize folded in)
    if (fold && threadIdx.x < 64) {
        int c = threadIdx.x;
        float sum = ST[ST_SUM + c], sq = ST[ST_SQ + c];
        float m   = sum / (float)NP;
        float var = sq / (float)NP - m * m;
        float s   = bng[c] * rsqrtf(var + 1e-5f);
        sS[c] = s; sT[c] = bnb[c] - m * s;
    }
    __syncthreads();

    // block 0: flush previous stage's extractor into AC
    if (blockIdx.x == 0 && threadIdx.x < 64) {
        int h = threadIdx.x;
        float o = eb1[h];
        for (int c = 0; c < eC; c++) {
            float str, stot;
            if (STA) { str = STA[c]; stot = STA[64 + c]; }
            else {
                float s = sS[c], t = sT[c];
                str  = ST[ST_TR  + c] * s + 512.f * t;
                stot = ST[ST_SUM + c] * s + (float)NP * t;
            }
            o += ew1[h * eC + c] * (str / 512.f)
               + ew2[h * eC + c] * ((stot - str) / (512.f * 511.f));
        }
        osh[h] = o;
    }
    __syncthreads();
    if (blockIdx.x == 0 && threadIdx.x < 64) {
        int h = threadIdx.x;
        float a = osh[h];
        for (int k = 0; k < 64; k++) a += ew3[h * 64 + k] * fmaxf(osh[k], 0.f);
        AC[h] += a;
    }

    for (int i = threadIdx.x; i < 64 * Ct; i += 256) {
        int o = i / Ct, c = i - o * Ct;
        float s = fold ? sS[c] : 1.f;
        Ws1[o * ld2 + c] = __float2bfloat16_rn(W1[i] * s);
        Ws2[o * ld2 + c] = __float2bfloat16_rn(W2[i] * s);
    }
    if (threadIdx.x < 64) {
        int o = threadIdx.x;
        float a1 = b1[o], a2 = b2[o];
        if (fold)
            for (int c = 0; c < Ct; c++) {
                float t = sT[c];
                a1 += W1[o * Ct + c] * t;
                a2 += W2[o * Ct + c] * t;
            }
        bs1[o] = a1; bs2[o] = a2;
    }
    __syncthreads();

    const int lane = threadIdx.x & 31;
    const int wid  = threadIdx.x >> 5;
    const int cg = wid & 3, rg = wid >> 2;
    const int lq = lane & 3, lr = lane >> 2;
    const int lml = lane & 15, lmh = (lane >> 4) << 3;
    const int nch = Ct >> 5;                // 1 or 2

    float bb1[2][2], bb2[2][2];
#pragma unroll
    for (int mi = 0; mi < 2; mi++) {
        int o0 = rg * 32 + mi * 16 + lr;
        bb1[mi][0] = bs1[o0]; bb1[mi][1] = bs1[o0 + 8];
        bb2[mi][0] = bs2[o0]; bb2[mi][1] = bs2[o0 + 8];
    }

    for (int t = 0; t < 2; t++) {
        const int p0 = blockIdx.x * 256 + t * 128;

        float acc1[2][4][4], acc2[2][4][4];
#pragma unroll
        for (int mi = 0; mi < 2; mi++)
#pragma unroll
            for (int nj = 0; nj < 4; nj++)
#pragma unroll
                for (int q = 0; q < 4; q++) { acc1[mi][nj][q] = 0.f; acc2[mi][nj][q] = 0.f; }

        // stage all k-chunks (<=2) up front
        for (int c = 0; c < nch; c++) {
            bf16* Ub = Us + c * (32 * 136);
            for (int i = threadIdx.x; i < 512; i += 256) {
                int kk = i >> 4, c8 = (i & 15) << 3;
                cp16(Ub + kk * 136 + c8, in + (size_t)(c * 32 + kk) * NP + p0 + c8);
            }
            CP_COMMIT();
        }

        auto computeChunk = [&](const bf16* Ub, int k0g) {
#pragma unroll
            for (int kk = 0; kk < 32; kk += 16) {
                uint32_t a1[2][4], a2[2][4], bq[2][4];
#pragma unroll
                for (int mi = 0; mi < 2; mi++) {
                    int r = rg * 32 + mi * 16 + lml;
                    LDSM4(a1[mi], smaddr(Ws1 + r * ld2 + k0g + kk + lmh));
                    LDSM4(a2[mi], smaddr(Ws2 + r * ld2 + k0g + kk + lmh));
                }
#pragma unroll
                for (int njp = 0; njp < 2; njp++)
                    LDSM4T(bq[njp], smaddr(Ub + (kk + lml) * 136 + cg * 32 + njp * 16 + lmh));
#pragma unroll
                for (int mi = 0; mi < 2; mi++)
#pragma unroll
                    for (int njp = 0; njp < 2; njp++) {
                        MMA_BF16(acc1[mi][2*njp],   a1[mi], (bq[njp]));
                        MMA_BF16(acc1[mi][2*njp+1], a1[mi], (bq[njp]+2));
                        MMA_BF16(acc2[mi][2*njp],   a2[mi], (bq[njp]));
                        MMA_BF16(acc2[mi][2*njp+1], a2[mi], (bq[njp]+2));
                    }
            }
        };

        if (nch == 2) {
            CP_WAIT(1); __syncthreads();
            computeChunk(Us, 0);
            CP_WAIT(0); __syncthreads();
            computeChunk(Us + 32 * 136, 32);
        } else {
            CP_WAIT(0); __syncthreads();
            computeChunk(Us, 0);
        }

        // dual epilogue: O1 staged in Us area, O2 in Os2; single sync phase
        bf16* Os1 = Us;                             // [64][136]
        __syncthreads();
#pragma unroll
        for (int mi = 0; mi < 2; mi++) {
            int o0 = rg * 32 + mi * 16 + lr, o1 = o0 + 8;
#pragma unroll
            for (int nj = 0; nj < 4; nj++) {
                int col = cg * 32 + nj * 8 + 2 * lq;
                *(bf162*)(Os1 + o0 * 136 + col) =
                    __floats2bfloat162_rn(acc1[mi][nj][0] + bb1[mi][0], acc1[mi][nj][1] + bb1[mi][0]);
                *(bf162*)(Os1 + o1 * 136 + col) =
                    __floats2bfloat162_rn(acc1[mi][nj][2] + bb1[mi][1], acc1[mi][nj][3] + bb1[mi][1]);
                *(bf162*)(Os2 + o0 * 136 + col) =
                    __floats2bfloat162_rn(acc2[mi][nj][0] + bb2[mi][0], acc2[mi][nj][1] + bb2[mi][0]);
                *(bf162*)(Os2 + o1 * 136 + col) =
                    __floats2bfloat162_rn(acc2[mi][nj][2] + bb2[mi][1], acc2[mi][nj][3] + bb2[mi][1]);
            }
        }
        __syncthreads();
        for (int i = threadIdx.x * 8; i < 64 * 128; i += 2048) {
            int o = i >> 7, c = i & 127;
            *(float4*)(O1 + (size_t)o * NP + p0 + c) = *(float4*)(Os1 + o * 136 + c);
            *(float4*)(O2 + (size_t)o * NP + p0 + c) = *(float4*)(Os2 + o * 136 + c);
        }
        __syncthreads();        // Us reused for next tile's staging
    }
}

// ---------------- batched 512^3 bf16 GEMM, persistent blocks -----------------
#define LDA 72      // 144B row stride
#define LDB 136     // 272B row stride
#define STG (128*LDA + 64*LDB)   // bf16 elems per stage = 17920
#define MMA_GRID 296             // 2 blocks x 148 SMs
__global__ __launch_bounds__(256, 2) void k_mma(const bf16* __restrict__ A,
                                                const bf16* __restrict__ B,
                                                bf16* __restrict__ C,
                                                float* __restrict__ ST,
                                                const float* __restrict__ bng,
                                                const float* __restrict__ bnb,
                                                int fold) {
    extern __shared__ bf16 dsm[];                  // 2 stages
    const int tid  = threadIdx.x;
    const int lane = tid & 31, wid = tid >> 5;
    const int wr = wid >> 1, wc = wid & 1;
    const int lq = lane & 3, lr = lane >> 2;
    const int lml = lane & 15, lmh = (lane >> 4) << 3;

    // block 0: snapshot s,t for mix4, then reset raw accumulators
    if (blockIdx.x == 0) {
        if (fold && tid < 64) {
            int c = tid;
            float sum = ST[ST_SUM + c], sq = ST[ST_SQ + c];
            float m   = sum / (float)NP;
            float var = sq / (float)NP - m * m;
            float s   = bng[c] * rsqrtf(var + 1e-5f);
            ST[ST_S + c] = s; ST[ST_T + c] = bnb[c] - m * s;
        }
        __syncthreads();
        if (tid < 192) ST[ST_SUM + tid] = 0.f;
    }

    for (int tile = blockIdx.x; tile < 1024; tile += MMA_GRID) {
        const int ch = tile >> 4;
        const int rowBase = ((tile >> 2) & 3) * 128;
        const int colBase = (tile & 3) * 128;
        const bf16* Ab = A + (size_t)ch * NP;
        const bf16* Bb = B + (size_t)ch * NP;
        bf16*       Cb = C + (size_t)ch * NP;

        float acc[2][8][4];
#pragma unroll
        for (int mi = 0; mi < 2; mi++)
#pragma unroll
            for (int nj = 0; nj < 8; nj++)
#pragma unroll
                for (int q = 0; q < 4; q++) acc[mi][nj][q] = 0.f;

        auto loadTile = [&](int t, int s) {
            bf16* As = dsm + s * STG;
            bf16* Bs = As + 128 * LDA;
            int k0 = t * 64;
#pragma unroll
            for (int i = 0; i < 4; i++) {              // A: 128 rows x 64 bf16
                int lin = tid + i * 256;
                int r = lin >> 3, kc = (lin & 7) << 3;
                cp16(As + r * LDA + kc, Ab + (size_t)(rowBase + r) * NN + k0 + kc);
            }
#pragma unroll
            for (int i = 0; i < 4; i++) {              // B: 64 rows x 128 bf16
                int lin = tid + i * 256;
                int kk = lin >> 4, c8 = (lin & 15) << 3;
                cp16(Bs + kk * LDB + c8, Bb + (size_t)(k0 + kk) * NN + colBase + c8);
            }
            CP_COMMIT();
        };

        loadTile(0, 0);
        for (int t = 0; t < 8; t++) {                  // k-tiles of 64
            if (t < 7) {
                loadTile(t + 1, (t + 1) & 1);
                CP_WAIT(1);
            } else {
                CP_WAIT(0);
            }
            __syncthreads();
            const bf16* As = dsm + (t & 1) * STG;
            const bf16* Bs = As + 128 * LDA;
#pragma unroll
            for (int kk = 0; kk < 64; kk += 16) {
                uint32_t a[2][4], bq[4][4];
#pragma unroll
                for (int mi = 0; mi < 2; mi++) {
                    int r = wr * 32 + mi * 16 + lml;
                    LDSM4(a[mi], smaddr(As + r * LDA + kk + lmh));
                }
#pragma unroll
                for (int njp = 0; njp < 4; njp++)
                    LDSM4T(bq[njp], smaddr(Bs + (kk + lml) * LDB + wc * 64 + njp * 16 + lmh));
#pragma unroll
                for (int mi = 0; mi < 2; mi++)
#pragma unroll
                    for (int njp = 0; njp < 4; njp++) {
                        MMA_BF16(acc[mi][2*njp],   a[mi], (bq[njp]));
                        MMA_BF16(acc[mi][2*njp+1], a[mi], (bq[njp]+2));
                    }
            }
            __syncthreads();
        }

        // coalesced epilogue: stage 128x128 tile in smem (row stride 136)
        bf16* Cs = dsm;
#pragma unroll
        for (int mi = 0; mi < 2; mi++) {
            int r0 = wr * 32 + mi * 16 + lr;
#pragma unroll
            for (int nj = 0; nj < 8; nj++) {
                int col = wc * 64 + nj * 8 + 2 * lq;
                *(bf162*)(Cs + r0 * 136 + col) =
                    __floats2bfloat162_rn(acc[mi][nj][0], acc[mi][nj][1]);
                *(bf162*)(Cs + (r0 + 8) * 136 + col) =
                    __floats2bfloat162_rn(acc[mi][nj][2], acc[mi][nj][3]);
            }
        }
        __syncthreads();
        for (int i = tid * 8; i < 128 * 128; i += 2048) {
            int r = i >> 7, c = i & 127;
            *(float4*)(Cb + (size_t)(rowBase + r) * NN + colBase + c) =
                *(float4*)(Cs + r * 136 + c);
        }
        __syncthreads();        // dsm reused by next tile's loads
    }
}

// ---------------- mix4: concat(M, cur) -> out (bf16), stats epilogue ---------
// 2 position-tiles per block; 4-buffer cp.async staging (all chunks in flight).
__global__ __launch_bounds__(256) void k_mix4(
    const bf16* __restrict__ Mt, const bf16* __restrict__ cur, int C2,
    const float* __restrict__ W, const float* __restrict__ bias,
    int fold, bf16* __restrict__ out, float* __restrict__ ST) {
    const int Ct = 64 + C2;
    const int ld2 = Ct + 8;
    extern __shared__ char shraw[];
    bf16*  Ws = (bf16*)shraw;               // [64][ld2]
    float* bs = (float*)(Ws + 64 * ld2);    // 64
    bf16*  Us = (bf16*)(bs + 64);           // 4 x [32][136]
    float* sSum = (float*)(Us + 4 * 32 * 136);  // 64
    float* sSq  = sSum + 64;                // 64
    float* sTr  = sSq + 64;                 // 64

    for (int i = threadIdx.x; i < 64 * Ct; i += 256) {
        int o = i / Ct, c = i - o * Ct;
        float s = (c >= 64 && fold) ? ST[ST_S + c - 64] : 1.f;
        Ws[o * ld2 + c] = __float2bfloat16_rn(W[i] * s);
    }
    if (threadIdx.x < 64) {
        int o = threadIdx.x;
        float a = bias[o];
        if (fold)
            for (int c = 64; c < Ct; c++) a += W[o * Ct + c] * ST[ST_T + c - 64];
        bs[o] = a;
    }
    if (threadIdx.x < 192) sSum[threadIdx.x] = 0.f;   // zeros sum/sq/tr
    __syncthreads();

    const int lane = threadIdx.x & 31;
    const int wid  = threadIdx.x >> 5;
    const int cg = wid & 3, rg = wid >> 2;
    const int lq = lane & 3, lr = lane >> 2;
    const int lml = lane & 15, lmh = (lane >> 4) << 3;
    const int nch = Ct >> 5;                // 3 or 4

    float bb[2][2];
#pragma unroll
    for (int mi = 0; mi < 2; mi++) {
        int o0 = rg * 32 + mi * 16 + lr;
        bb[mi][0] = bs[o0]; bb[mi][1] = bs[o0 + 8];
    }

    for (int t = 0; t < 2; t++) {
        const int p0 = blockIdx.x * 256 + t * 128;

        float acc[2][4][4];
#pragma unroll
        for (int mi = 0; mi < 2; mi++)
#pragma unroll
            for (int nj = 0; nj < 4; nj++)
#pragma unroll
                for (int q = 0; q < 4; q++) acc[mi][nj][q] = 0.f;

        // stage all k-chunks (3 or 4) up front
        for (int c = 0; c < nch; c++) {
            bf16* Ub = Us + c * (32 * 136);
            int cb = c * 32;
            for (int i = threadIdx.x; i < 512; i += 256) {
                int kk = i >> 4, c8 = (i & 15) << 3;
                int ch = cb + kk;
                const bf16* src = (ch < 64) ? Mt + (size_t)ch * NP
                                            : cur + (size_t)(ch - 64) * NP;
                cp16(Ub + kk * 136 + c8, src + p0 + c8);
            }
            CP_COMMIT();
        }

        auto computeChunk = [&](const bf16* Ub, int k0g) {
#pragma unroll
            for (int kk = 0; kk < 32; kk += 16) {
                uint32_t a[2][4], bq[2][4];
#pragma unroll
                for (int mi = 0; mi < 2; mi++) {
                    int r = rg * 32 + mi * 16 + lml;
                    LDSM4(a[mi], smaddr(Ws + r * ld2 + k0g + kk + lmh));
                }
#pragma unroll
                for (int njp = 0; njp < 2; njp++)
                    LDSM4T(bq[njp], smaddr(Ub + (kk + lml) * 136 + cg * 32 + njp * 16 + lmh));
#pragma unroll
                for (int mi = 0; mi < 2; mi++)
#pragma unroll
                    for (int njp = 0; njp < 2; njp++) {
                        MMA_BF16(acc[mi][2*njp],   a[mi], (bq[njp]));
                        MMA_BF16(acc[mi][2*njp+1], a[mi], (bq[njp]+2));
                    }
            }
        };

        if (nch == 4) {
            CP_WAIT(3); __syncthreads(); computeChunk(Us,             0);
            CP_WAIT(2); __syncthreads(); computeChunk(Us + 32*136,   32);
            CP_WAIT(1); __syncthreads(); computeChunk(Us + 2*32*136, 64);
            CP_WAIT(0); __syncthreads(); computeChunk(Us + 3*32*136, 96);
        } else {
            CP_WAIT(2); __syncthreads(); computeChunk(Us,             0);
            CP_WAIT(1); __syncthreads(); computeChunk(Us + 32*136,   32);
            CP_WAIT(0); __syncthreads(); computeChunk(Us + 2*32*136, 64);
        }

        int dp = ((p0 + 512) / 513) * 513;          // diagonal column inside tile
        bool hasDiag = (dp < p0 + 128);
        bf16* Os = Us;                              // [64][136] staging in U area
        __syncthreads();

#pragma unroll
        for (int mi = 0; mi < 2; mi++) {
            int o0 = rg * 32 + mi * 16 + lr, o1 = o0 + 8;
            float b0 = bb[mi][0], b1v = bb[mi][1];
            float s0 = 0.f, q0 = 0.f, s1 = 0.f, q1 = 0.f;
#pragma unroll
            for (int nj = 0; nj < 4; nj++) {
                int col = cg * 32 + nj * 8 + 2 * lq;
                float v00 = acc[mi][nj][0] + b0, v01 = acc[mi][nj][1] + b0;
                float v10 = acc[mi][nj][2] + b1v, v11 = acc[mi][nj][3] + b1v;
                if (out) {
                    *(bf162*)(Os + o0 * 136 + col) = __floats2bfloat162_rn(v00, v01);
                    *(bf162*)(Os + o1 * 136 + col) = __floats2bfloat162_rn(v10, v11);
                }
                s0 += v00 + v01; q0 += v00 * v00 + v01 * v01;
                s1 += v10 + v11; q1 += v10 * v10 + v11 * v11;
                if (hasDiag) {
                    int gcol = p0 + col;
                    if (gcol == dp)     { atomicAdd(&sTr[o0], v00); atomicAdd(&sTr[o1], v10); }
                    if (gcol + 1 == dp) { atomicAdd(&sTr[o0], v01); atomicAdd(&sTr[o1], v11); }
                }
            }
#pragma unroll
            for (int off = 1; off < 4; off <<= 1) {
                s0 += __shfl_xor_sync(0xffffffffu, s0, off);
                q0 += __shfl_xor_sync(0xffffffffu, q0, off);
                s1 += __shfl_xor_sync(0xffffffffu, s1, off);
                q1 += __shfl_xor_sync(0xffffffffu, q1, off);
            }
            if (lq == 0) {
                atomicAdd(&sSum[o0], s0); atomicAdd(&sSq[o0], q0);
                atomicAdd(&sSum[o1], s1); atomicAdd(&sSq[o1], q1);
            }
        }
        __syncthreads();
        if (out) {
            for (int i = threadIdx.x * 8; i < 64 * 128; i += 2048) {
                int o = i >> 7, c = i & 127;
                *(float4*)(out + (size_t)o * NP + p0 + c) = *(float4*)(Os + o * 136 + c);
            }
            __syncthreads();        // Us reused for next tile's staging
        }
    }

    if (threadIdx.x < 64) {
        int c = threadIdx.x;
        atomicAdd(&ST[ST_SUM + c], sSum[c]);
        atomicAdd(&ST[ST_SQ  + c], sSq[c]);
        if (sTr[c] != 0.f) atomicAdd(&ST[ST_TR + c], sTr[c]);
    }
}

// ---------------- head: layer-2 finalize + extractor + classifier ------------
__global__ void k_head(float* __restrict__ ST,
                       const float* __restrict__ g, const float* __restrict__ b,
                       const float* __restrict__ ew1, const float* __restrict__ eb1,
                       const float* __restrict__ ew2, const float* __restrict__ ew3,
                       const float* __restrict__ acc,
                       const float* __restrict__ ac_w, const float* __restrict__ ac_b,
                       const float* __restrict__ fl_w, const float* __restrict__ fl_b,
                       float* __restrict__ out) {
    __shared__ float o[64], t[64], osh[64], lg[10];
    int h = threadIdx.x;                               // 64 threads
    {
        float sum = ST[ST_SUM + h], sq = ST[ST_SQ + h], tr = ST[ST_TR + h];
        float m   = sum / (float)NP;
        float var = sq / (float)NP - m * m;
        float s   = g[h] * rsqrtf(var + 1e-5f);
        float tt  = b[h] - m * s;
        o[h] = tr * s + 512.f * tt;                    // str
        t[h] = sum * s + (float)NP * tt;               // stot
    }
    __syncthreads();
    float oo = eb1[h];
    for (int c = 0; c < 64; c++)
        oo += ew1[h * 64 + c] * (o[c] / 512.f)
            + ew2[h * 64 + c] * ((t[c] - o[c]) / (512.f * 511.f));
    osh[h] = oo;
    __syncthreads();
    float a = osh[h];
    for (int k = 0; k < 64; k++) a += ew3[h * 64 + k] * fmaxf(osh[k], 0.f);
    float accv = acc[h] + a;
    __syncthreads();
    o[h] = fmaxf(accv, 0.f) / (float)NL;
    __syncthreads();
    float s2 = ac_b[h];
    for (int k = 0; k < 64; k++) s2 += ac_w[h * 64 + k] * o[k];
    t[h] = o[h] + fmaxf(s2, 0.f);
    __syncthreads();
    if (h < 10) {
        float l = fl_b[h];
        for (int k = 0; k < 64; k++) l += fl_w[h * 64 + k] * t[k];
        lg[h] = l;
    }
    __syncthreads();
    if (h < 10) {
        float m = -1e30f;
        for (int i = 0; i < 10; i++) m = fmaxf(m, lg[i]);
        float se = 0.f;
        for (int i = 0; i < 10; i++) se += expf(lg[i] - m);
        out[h] = lg[h] - m - logf(se);
    }
}

// ---------------- launch -----------------------------------------------------
extern "C" void kernel_launch(void* const* d_in, const int* in_sizes, int n_in,
                              void* d_out, int out_size) {
    const float* x     = (const float*)d_in[0];
    const int*   ei    = (const int*)  d_in[1];
    const float* np1_w = (const float*)d_in[2];
    const float* np1_b = (const float*)d_in[3];
    const float* np2_w = (const float*)d_in[4];
    const float* np3_w = (const float*)d_in[5];
    const float* c0m1w = (const float*)d_in[6];
    const float* c0m1b = (const float*)d_in[7];
    const float* c0m2w = (const float*)d_in[8];
    const float* c0m2b = (const float*)d_in[9];
    const float* c0m4w = (const float*)d_in[10];
    const float* c0m4b = (const float*)d_in[11];
    const float* cm1w  = (const float*)d_in[12];
    const float* cm1b  = (const float*)d_in[13];
    const float* cm2w  = (const float*)d_in[14];
    const float* cm2b  = (const float*)d_in[15];
    const float* cm4w  = (const float*)d_in[16];
    const float* cm4b  = (const float*)d_in[17];
    const float* bn_g  = (const float*)d_in[18];
    const float* bn_b  = (const float*)d_in[19];
    const float* fe1w  = (const float*)d_in[20];
    const float* fe1b  = (const float*)d_in[21];
    const float* fe2w  = (const float*)d_in[22];
    const float* fe3w  = (const float*)d_in[23];
    const float* ac_w  = (const float*)d_in[24];
    const float* ac_b  = (const float*)d_in[25];
    const float* fl_w  = (const float*)d_in[26];
    const float* fl_b  = (const float*)d_in[27];

    float *ST, *AC;
    bf16 *Ub, *V0, *V1, *O1, *O2, *M;
    cudaGetSymbolAddress((void**)&Ub, g_Ub);
    cudaGetSymbolAddress((void**)&V0, g_V0);
    cudaGetSymbolAddress((void**)&V1, g_V1);
    cudaGetSymbolAddress((void**)&O1, g_O1);
    cudaGetSymbolAddress((void**)&O2, g_O2);
    cudaGetSymbolAddress((void**)&M,  g_M);
    cudaGetSymbolAddress((void**)&ST, g_ST);
    cudaGetSymbolAddress((void**)&AC, g_AC);

    static bool attr_done = false;
    if (!attr_done) {
        cudaFuncSetAttribute(k_mma,   cudaFuncAttributeMaxDynamicSharedMemorySize, 2 * STG * 2);
        cudaFuncSetAttribute(k_mixAB, cudaFuncAttributeMaxDynamicSharedMemorySize, 64 * 1024);
        cudaFuncSetAttribute(k_mix4,  cudaFuncAttributeMaxDynamicSharedMemorySize, 64 * 1024);
        attr_done = true;
    }

    k_zero<<<(4u * NP) / 256, 256>>>((uint4*)Ub, AC, ST);
    k_scatter<<<(EE * 32) / 256, 256>>>(x, ei, Ub);
    k_ext_stats<<<TWOF, 256>>>(Ub, ST + ST_ATR);

    const bf16* cur = Ub;
    for (int l = 0; l < NL; l++) {
        const int Cin = l ? 64 : TWOF;
        const int fold = (l > 0) ? 1 : 0;
        const float* m1w = l ? cm1w + (l - 1) * 64 * 64  : c0m1w;
        const float* m1b = l ? cm1b + (l - 1) * 64       : c0m1b;
        const float* m2w = l ? cm2w + (l - 1) * 64 * 64  : c0m2w;
        const float* m2b = l ? cm2b + (l - 1) * 64       : c0m2b;
        const float* m4w = l ? cm4w + (l - 1) * 64 * 128 : c0m4w;
        const float* m4b = l ? cm4b + (l - 1) * 64       : c0m4b;
        const float* pbg = l ? bn_g + 64 * (l - 1) : nullptr;  // prev-layer bn
        const float* pbb = l ? bn_b + 64 * (l - 1) : nullptr;
        // extractor to flush: layer 0 -> adjacency (np), else fe of layer l-1
        const float* sta = l ? nullptr : (ST + ST_ATR);
        const float* ew1 = l ? fe1w + (l - 1) * 64 * 64 : np1_w;
        const float* eb1 = l ? fe1b + (l - 1) * 64      : np1_b;
        const float* ew2 = l ? fe2w + (l - 1) * 64 * 64 : np2_w;
        const float* ew3 = l ? fe3w + (l - 1) * 64 * 64 : np3_w;
        const int    eC  = l ? 64 : TWOF;

        size_t shAB = (size_t)(2 * 64 * (Cin + 8) + 2 * 32 * 136 + 64 * 136) * 2
                      + 2 * 64 * 4;
        k_mixAB<<<1024, 256, shAB>>>(cur, Cin, m1w, m1b, m2w, m2b, ST, fold,
                                     pbg, pbb, sta, ew1, eb1, ew2, ew3, eC, AC,
                                     O1, O2);

        k_mma<<<MMA_GRID, 256, 2 * STG * 2>>>(O1, O2, M, ST, pbg, pbb, fold);

        bf16* nxt = (l == 0) ? V0 : ((l == 1) ? V1 : nullptr);
        size_t sh4 = (size_t)(64 * (64 + Cin + 8) + 4 * 32 * 136) * 2 + (64 + 192) * 4;
        k_mix4<<<1024, 256, sh4>>>(M, cur, Cin, m4w, m4b, fold, nxt, ST);

        cur = nxt;
    }

    k_head<<<1, 64>>>(ST, bn_g + 128, bn_b + 128,
                      fe1w + 2 * 64 * 64, fe1b + 2 * 64,
                      fe2w + 2 * 64 * 64, fe3w + 2 * 64 * 64,
                      AC, ac_w, ac_b, fl_w, fl_b, (float*)d_out);
}